// round 4
// baseline (speedup 1.0000x reference)
#include <cuda_runtime.h>
#include <math.h>

#define Bsz 32
#define Vn 197
#define Tn 512
#define Dn 768
#define Mfc (Bsz*Tn)   // 16384

// ---------------- scratch (static device memory; no runtime allocs) ----------------
__device__ float g_S[Bsz*Vn*Tn];        // amap raw bmm result
__device__ float g_h[Bsz*Tn*Dn];        // relu(fc1(txt))
__device__ float g_rowsum[Bsz*Vn];      // -> va after act
__device__ float g_colsum[Bsz*Tn];      // -> ta after act
__device__ float g_vcls[Bsz*Dn];
__device__ float g_tcls[Bsz*Dn];
__device__ float g_vemb[Bsz*Dn];
__device__ float g_temb[Bsz*Dn];
__device__ float g_vhat[Bsz*Dn];
__device__ float g_that[Bsz*Dn];
__device__ float g_pred[Bsz*Tn];
__device__ float g_vs[Bsz], g_ts[Bsz], g_lam[Bsz], g_per[Bsz], g_rowloss[Bsz];
__device__ float g_A[81], g_Bq[9], g_K[25], g_C[1];
__device__ float g_nvarv[Dn], g_nvart[Dn];

// ---------------- conv composition precompute ----------------
__global__ void conv_pre(const float* __restrict__ w1, const float* __restrict__ b1,
                         const float* __restrict__ w2, const float* __restrict__ b2) {
    int t = threadIdx.x;
    if (t < 81) {
        int q = t / 9, s = t % 9;
        float a = 0.f;
        for (int c = 0; c < 64; c++) a += w2[c*9 + q] * w1[c*9 + s];
        g_A[t] = a;
    } else if (t < 90) {
        int q = t - 81;
        float a = 0.f;
        for (int c = 0; c < 64; c++) a += w2[c*9 + q] * b1[c];
        g_Bq[q] = a;
    }
    __syncthreads();
    if (t < 25) {
        int u = t / 5, w = t % 5;
        float a = 0.f;
        for (int qi = 0; qi < 3; qi++) for (int si = 0; si < 3; si++) if (qi + si == u)
            for (int qj = 0; qj < 3; qj++) for (int sj = 0; sj < 3; sj++) if (qj + sj == w)
                a += g_A[(qi*3 + qj)*9 + si*3 + sj];
        g_K[t] = a;
    }
    if (t == 127) {
        float a = b2[0];
        for (int q = 0; q < 9; q++) a += g_Bq[q];
        g_C[0] = a;
    }
}

__global__ void zero_rc() {
    int i = blockIdx.x * blockDim.x + threadIdx.x;
    if (i < Bsz*Vn) g_rowsum[i] = 0.f;
    if (i < Bsz*Tn) g_colsum[i] = 0.f;
}

// ---------------- batched GEMM: S[b] = vis[b] (197x768) @ txt[b]^T (768x512) ----------------
// Software-pipelined: next k-tile is prefetched into registers before the
// current tile's FFMA loop, hiding LDG latency under compute.
__global__ __launch_bounds__(256) void bmm_kernel(const float* __restrict__ vis,
                                                  const float* __restrict__ txt) {
    int b = blockIdx.z;
    const float* A  = vis + (size_t)b * Vn * Dn;
    const float* Bm = txt + (size_t)b * Tn * Dn;
    float* C = g_S + (size_t)b * Vn * Tn;
    __shared__ float As[8][128];
    __shared__ float Bs[8][128];
    int tid = threadIdx.x;
    int tx = tid & 15, ty = tid >> 4;
    int m0 = blockIdx.y * 128, n0 = blockIdx.x * 128;
    int lr = tid >> 1, lk = (tid & 1) * 4;
    float acc[8][8];
#pragma unroll
    for (int i = 0; i < 8; i++)
#pragma unroll
        for (int j = 0; j < 8; j++) acc[i][j] = 0.f;
    bool aValid = (m0 + lr) < Vn;
    const float* aPtr = A + (size_t)(m0 + lr) * Dn + lk;
    const float* bPtr = Bm + (size_t)(n0 + lr) * Dn + lk;
    // prologue: fetch tile 0
    float4 a4 = aValid ? *(const float4*)(aPtr) : make_float4(0.f,0.f,0.f,0.f);
    float4 b4 = *(const float4*)(bPtr);
    for (int kk = 0; kk < Dn; kk += 8) {
        __syncthreads();
        As[lk+0][lr] = a4.x; As[lk+1][lr] = a4.y; As[lk+2][lr] = a4.z; As[lk+3][lr] = a4.w;
        Bs[lk+0][lr] = b4.x; Bs[lk+1][lr] = b4.y; Bs[lk+2][lr] = b4.z; Bs[lk+3][lr] = b4.w;
        __syncthreads();
        if (kk + 8 < Dn) {   // prefetch next tile; latency hidden by FFMA below
            a4 = aValid ? *(const float4*)(aPtr + kk + 8) : make_float4(0.f,0.f,0.f,0.f);
            b4 = *(const float4*)(bPtr + kk + 8);
        }
#pragma unroll
        for (int k = 0; k < 8; k++) {
            float4 a0 = *(const float4*)&As[k][ty*8];
            float4 a1 = *(const float4*)&As[k][ty*8+4];
            float4 b0 = *(const float4*)&Bs[k][tx*8];
            float4 b1 = *(const float4*)&Bs[k][tx*8+4];
            float av[8] = {a0.x,a0.y,a0.z,a0.w,a1.x,a1.y,a1.z,a1.w};
            float bv[8] = {b0.x,b0.y,b0.z,b0.w,b1.x,b1.y,b1.z,b1.w};
#pragma unroll
            for (int i = 0; i < 8; i++)
#pragma unroll
                for (int j = 0; j < 8; j++) acc[i][j] += av[i] * bv[j];
        }
    }
#pragma unroll
    for (int i = 0; i < 8; i++) {
        int m = m0 + ty*8 + i;
        if (m < Vn) {
#pragma unroll
            for (int j = 0; j < 8; j++) C[(size_t)m * Tn + n0 + tx*8 + j] = acc[i][j];
        }
    }
}

// ---------------- fused conv(5x5 eq) + relu + row/col reduce ----------------
__global__ void conv_kernel(const float* __restrict__ b2ptr) {
    int b = blockIdx.z;
    int v0 = blockIdx.y * 32, t0 = blockIdx.x * 64;
    __shared__ float sh[36][68];
    __shared__ float shA[81], shB[9], shK[25];
    __shared__ float shRow[32], shCol[64];
    int tid = threadIdx.y * 64 + threadIdx.x;
    if (tid < 81) shA[tid] = g_A[tid];
    if (tid < 9)  shB[tid] = g_Bq[tid];
    if (tid < 25) shK[tid] = g_K[tid];
    if (tid < 32) shRow[tid] = 0.f;
    if (tid < 64) shCol[tid] = 0.f;
    float cC  = g_C[0];
    float b2v = b2ptr[0];
    const float* Sb = g_S + (size_t)b * Vn * Tn;
    for (int i = tid; i < 36*68; i += 256) {
        int r = i / 68, c = i % 68;
        int gv = v0 - 2 + r, gt = t0 - 2 + c;
        sh[r][c] = (gv >= 0 && gv < Vn && gt >= 0 && gt < Tn) ? Sb[(size_t)gv * Tn + gt] : 0.f;
    }
    __syncthreads();
    int tx = threadIdx.x;
    float colAcc = 0.f;
#pragma unroll
    for (int kk = 0; kk < 8; kk++) {
        int vl = threadIdx.y + kk * 4;
        int gv = v0 + vl, gt = t0 + tx;
        float z = 0.f;
        if (gv < Vn) {
            if (gv >= 1 && gv <= Vn-2 && gt >= 1 && gt <= Tn-2) {
                z = cC;
#pragma unroll
                for (int u = 0; u < 5; u++)
#pragma unroll
                    for (int w = 0; w < 5; w++) z += shK[u*5 + w] * sh[vl + u][tx + w];
            } else {
                z = b2v;
#pragma unroll
                for (int qi = 0; qi < 3; qi++)
#pragma unroll
                    for (int qj = 0; qj < 3; qj++) {
                        int pv = gv + qi - 1, pt = gt + qj - 1;
                        if (pv >= 0 && pv < Vn && pt >= 0 && pt < Tn) {
                            int q = qi*3 + qj;
                            z += shB[q];
#pragma unroll
                            for (int si = 0; si < 3; si++)
#pragma unroll
                                for (int sj = 0; sj < 3; sj++)
                                    z += shA[q*9 + si*3 + sj] * sh[vl + qi + si][tx + qj + sj];
                        }
                    }
            }
            z = fmaxf(z, 0.f);
        }
        float r = z;
        for (int o = 16; o; o >>= 1) r += __shfl_down_sync(0xffffffffu, r, o);
        if ((tid & 31) == 0 && gv < Vn) atomicAdd(&shRow[vl], r);
        colAcc += z;
    }
    atomicAdd(&shCol[tx], colAcc);
    __syncthreads();
    if (tid < 32 && v0 + tid < Vn) atomicAdd(&g_rowsum[b*Vn + v0 + tid], shRow[tid]);
    if (tid < 64) atomicAdd(&g_colsum[b*Tn + t0 + tid], shCol[tid]);
}

// rowsum -> va = sigmoid(sum/T); colsum -> ta = sigmoid(sum/V)
__global__ void act_kernel() {
    int i = blockIdx.x * blockDim.x + threadIdx.x;
    if (i < Bsz*Vn) g_rowsum[i] = 1.f / (1.f + expf(-g_rowsum[i] / (float)Tn));
    if (i < Bsz*Tn) g_colsum[i] = 1.f / (1.f + expf(-g_colsum[i] / (float)Vn));
}

// CLS means (attention-weighted)
__global__ void cls_kernel(const float* __restrict__ vis, const float* __restrict__ txt) {
    int b = blockIdx.y;
    int d = blockIdx.x * 256 + threadIdx.x;
    float acc = 0.f;
    for (int v = 0; v < Vn; v++) acc += g_rowsum[b*Vn + v] * vis[((size_t)b*Vn + v)*Dn + d];
    g_vcls[b*Dn + d] = acc / (float)Vn;
    float acc2 = 0.f;
    for (int t = 0; t < Tn; t++) acc2 += g_colsum[b*Tn + t] * txt[((size_t)b*Tn + t)*Dn + d];
    g_tcls[b*Dn + d] = acc2 / (float)Tn;
}

// ---------------- big GEMM: h = relu( diag(ta)*text @ fc1_w^T + fc1_b ) ----------------
// Same software pipeline as bmm_kernel.
__global__ __launch_bounds__(256) void fc_kernel(const float* __restrict__ txt,
                                                 const float* __restrict__ w1,
                                                 const float* __restrict__ b1) {
    __shared__ float As[8][128];
    __shared__ float Bs[8][128];
    int tid = threadIdx.x;
    int tx = tid & 15, ty = tid >> 4;
    int m0 = blockIdx.y * 128, n0 = blockIdx.x * 128;
    int lr = tid >> 1, lk = (tid & 1) * 4;
    float acc[8][8];
#pragma unroll
    for (int i = 0; i < 8; i++)
#pragma unroll
        for (int j = 0; j < 8; j++) acc[i][j] = 0.f;
    int gm = m0 + lr;                     // row in [0, 16384)
    float scl = g_colsum[gm];             // ta for (b,t)
    const float* aPtr = txt + (size_t)gm * Dn + lk;
    const float* bPtr = w1 + (size_t)(n0 + lr) * Dn + lk;
    // prologue: fetch tile 0
    float4 a4 = *(const float4*)(aPtr);
    float4 b4 = *(const float4*)(bPtr);
    for (int kk = 0; kk < Dn; kk += 8) {
        float4 as = a4;
        as.x *= scl; as.y *= scl; as.z *= scl; as.w *= scl;
        __syncthreads();
        As[lk+0][lr] = as.x; As[lk+1][lr] = as.y; As[lk+2][lr] = as.z; As[lk+3][lr] = as.w;
        Bs[lk+0][lr] = b4.x; Bs[lk+1][lr] = b4.y; Bs[lk+2][lr] = b4.z; Bs[lk+3][lr] = b4.w;
        __syncthreads();
        if (kk + 8 < Dn) {   // prefetch next tile
            a4 = *(const float4*)(aPtr + kk + 8);
            b4 = *(const float4*)(bPtr + kk + 8);
        }
#pragma unroll
        for (int k = 0; k < 8; k++) {
            float4 a0 = *(const float4*)&As[k][ty*8];
            float4 a1 = *(const float4*)&As[k][ty*8+4];
            float4 b0 = *(const float4*)&Bs[k][tx*8];
            float4 b1 = *(const float4*)&Bs[k][tx*8+4];
            float av[8] = {a0.x,a0.y,a0.z,a0.w,a1.x,a1.y,a1.z,a1.w};
            float bv[8] = {b0.x,b0.y,b0.z,b0.w,b1.x,b1.y,b1.z,b1.w};
#pragma unroll
            for (int i = 0; i < 8; i++)
#pragma unroll
                for (int j = 0; j < 8; j++) acc[i][j] += av[i] * bv[j];
        }
    }
#pragma unroll
    for (int i = 0; i < 8; i++) {
        int m = m0 + ty*8 + i;
#pragma unroll
        for (int j = 0; j < 8; j++) {
            int n = n0 + tx*8 + j;
            float v = acc[i][j] + b1[n];
            g_h[(size_t)m * Dn + n] = fmaxf(v, 0.f);
        }
    }
}

// pred = h @ fc2_w + fc2_b (one warp per row)
__global__ void pred_kernel(const float* __restrict__ w2, const float* __restrict__ b2) {
    int row = blockIdx.x * 8 + (threadIdx.x >> 5);
    int lane = threadIdx.x & 31;
    float acc = 0.f;
    for (int n = lane; n < Dn; n += 32) acc += g_h[(size_t)row * Dn + n] * w2[n];
    for (int o = 16; o; o >>= 1) acc += __shfl_down_sync(0xffffffffu, acc, o);
    if (lane == 0) g_pred[row] = acc + b2[0];
}

// masked per-sample sentiment MSE
__global__ void loss1_kernel(const float* __restrict__ sent, const int* __restrict__ lens) {
    int b = blockIdx.x, t = threadIdx.x;
    float s = sent[b*Tn + t];
    float p = g_pred[b*Tn + t];
    if (s == 0.f) p = 0.f;
    int len = lens[b];
    float e = 0.f;
    if (t < len) { float df = p - s; e = df * df; }
    __shared__ float red[512];
    red[t] = e; __syncthreads();
    for (int o = 256; o > 0; o >>= 1) { if (t < o) red[t] += red[t + o]; __syncthreads(); }
    if (t == 0) g_per[b] = red[0] / (float)len;
}

// small GEMMs: t_emb = tCLS@fc1^T + b, v_emb = vCLS@fc1^T + b
__global__ void emb_kernel(const float* __restrict__ w1, const float* __restrict__ b1) {
    int b = blockIdx.x;
    int which = blockIdx.y;
    const float* src = which ? g_vcls : g_tcls;
    float* dst = which ? g_vemb : g_temb;
    __shared__ float cls[Dn];
    int tid = threadIdx.x;
    for (int i = tid; i < Dn; i += 256) cls[i] = src[b*Dn + i];
    __syncthreads();
    for (int n = tid; n < Dn; n += 256) {
        const float4* wr = (const float4*)(w1 + (size_t)n * Dn);
        float acc = b1[n];
#pragma unroll 4
        for (int k4 = 0; k4 < Dn/4; k4++) {
            float4 w = wr[k4];
            acc += cls[k4*4+0]*w.x + cls[k4*4+1]*w.y + cls[k4*4+2]*w.z + cls[k4*4+3]*w.w;
        }
        dst[b*Dn + n] = acc;
    }
}

// v_s, t_s, lamda, normalized embeddings (one warp per batch row)
__global__ void tail1_kernel(const float* __restrict__ w2, const float* __restrict__ b2) {
    int b = threadIdx.x >> 5;
    int lane = threadIdx.x & 31;
    float sv = 0.f, st = 0.f, nv = 0.f, nt = 0.f;
    for (int d = lane; d < Dn; d += 32) {
        float ve = g_vemb[b*Dn + d], te = g_temb[b*Dn + d], wv = w2[d];
        sv += fmaxf(ve, 0.f) * wv;
        st += te * wv;
        nv += ve * ve; nt += te * te;
    }
    for (int o = 16; o; o >>= 1) {
        sv += __shfl_xor_sync(0xffffffffu, sv, o);
        st += __shfl_xor_sync(0xffffffffu, st, o);
        nv += __shfl_xor_sync(0xffffffffu, nv, o);
        nt += __shfl_xor_sync(0xffffffffu, nt, o);
    }
    float dnv = fmaxf(sqrtf(nv), 1e-12f), dnt = fmaxf(sqrtf(nt), 1e-12f);
    for (int d = lane; d < Dn; d += 32) {
        g_vhat[b*Dn + d] = g_vemb[b*Dn + d] / dnv;
        g_that[b*Dn + d] = g_temb[b*Dn + d] / dnt;
    }
    if (lane == 0) {
        float vs = sv + b2[0], ts = st + b2[0];
        g_vs[b] = vs; g_ts[b] = ts; g_lam[b] = fabsf(ts - vs);
    }
}

// per-row KL(contrast || sim)
__global__ void contrast_kernel() {
    int i = blockIdx.x;
    int w = threadIdx.x >> 5, lane = threadIdx.x & 31;
    __shared__ float shZ[32];
    float dot = 0.f;
    for (int d = lane; d < Dn; d += 32) dot += g_vhat[i*Dn + d] * g_that[w*Dn + d];
    for (int o = 16; o; o >>= 1) dot += __shfl_xor_sync(0xffffffffu, dot, o);
    if (lane == 0) shZ[w] = dot * 5.0f;   // /0.2
    __syncthreads();
    if (threadIdx.x < 32) {
        int j = threadIdx.x;
        float z = shZ[j];
        float cu = expf(-fabsf(g_vs[i] - g_ts[j]));
        float su = expf(z);
        float cs = cu, ss = su;
        for (int o = 16; o; o >>= 1) {
            cs += __shfl_xor_sync(0xffffffffu, cs, o);
            ss += __shfl_xor_sync(0xffffffffu, ss, o);
        }
        float c = cu / cs;
        float term = c * (logf(c) - (z - logf(ss)));
        for (int o = 16; o; o >>= 1) term += __shfl_xor_sync(0xffffffffu, term, o);
        if (j == 0) g_rowloss[i] = term;
    }
}

// per-dim variance over batch (ddof=1), l2-normalized over D
__global__ void varsem_kernel() {
    int d = threadIdx.x;  // 768 threads
    __shared__ float red[Dn];
    __shared__ float s_nv, s_nt;
    float mv = 0.f, mt = 0.f;
    for (int b = 0; b < Bsz; b++) { mv += g_vcls[b*Dn + d]; mt += g_tcls[b*Dn + d]; }
    mv /= 32.f; mt /= 32.f;
    float vv = 0.f, vt = 0.f;
    for (int b = 0; b < Bsz; b++) {
        float x = g_vcls[b*Dn + d] - mv; vv += x * x;
        float y = g_tcls[b*Dn + d] - mt; vt += y * y;
    }
    vv /= 31.f; vt /= 31.f;
    red[d] = vv * vv; __syncthreads();
    if (d < 256) red[d] += red[d + 512];
    __syncthreads();
    for (int s = 256; s > 0; s >>= 1) { if (d < s) red[d] += red[d + s]; __syncthreads(); }
    if (d == 0) s_nv = fmaxf(sqrtf(red[0]), 1e-12f);
    __syncthreads();
    red[d] = vt * vt; __syncthreads();
    if (d < 256) red[d] += red[d + 512];
    __syncthreads();
    for (int s = 256; s > 0; s >>= 1) { if (d < s) red[d] += red[d + s]; __syncthreads(); }
    if (d == 0) s_nt = fmaxf(sqrtf(red[0]), 1e-12f);
    __syncthreads();
    g_nvarv[d] = vv / s_nv;
    g_nvart[d] = vt / s_nt;
}

// final fused head -> out[0..31]
__global__ void final_kernel(const float* __restrict__ fw, const float* __restrict__ fb,
                             float* __restrict__ out) {
    int b = blockIdx.x;
    int tid = threadIdx.x;
    float acc = 0.f;
    for (int d = tid; d < Dn; d += 256) {
        float vc = g_vcls[b*Dn + d], tc = g_tcls[b*Dn + d];
        float sv = vc * (1.f + g_nvarv[d]);
        float st = tc * (1.f + g_nvart[d]);
        float f = 0.5f * (sv * st + g_vemb[b*Dn + d] * g_temb[b*Dn + d]);
        acc += f * fw[d];
    }
    __shared__ float red[256];
    red[tid] = acc; __syncthreads();
    for (int o = 128; o > 0; o >>= 1) { if (tid < o) red[tid] += red[tid + o]; __syncthreads(); }
    if (tid == 0) out[b] = red[0] + fb[0] + 0.1f * g_lam[b] - 0.5f;
}

__global__ void finalize_kernel(float* __restrict__ out, int out_size) {
    int t = threadIdx.x;  // 32
    float a = g_rowloss[t], p = g_per[t];
    for (int o = 16; o; o >>= 1) {
        a += __shfl_xor_sync(0xffffffffu, a, o);
        p += __shfl_xor_sync(0xffffffffu, p, o);
    }
    if (t == 0) { out[32] = a / 32.f; out[33] = p / 32.f; }
    // zero any padding the harness might check
    for (int i = 34 + t; i < out_size; i += 32) out[i] = 0.f;
}

// ---------------- launch ----------------
extern "C" void kernel_launch(void* const* d_in, const int* in_sizes, int n_in,
                              void* d_out, int out_size) {
    const float* vis   = (const float*)d_in[0];
    const float* txt   = (const float*)d_in[1];
    const float* sent  = (const float*)d_in[2];
    const int*   lens  = (const int*)d_in[3];
    const float* fc1w  = (const float*)d_in[4];
    const float* fc1b  = (const float*)d_in[5];
    const float* fc2w  = (const float*)d_in[6];
    const float* fc2b  = (const float*)d_in[7];
    const float* c1w   = (const float*)d_in[8];
    const float* c1b   = (const float*)d_in[9];
    const float* c2w   = (const float*)d_in[10];
    const float* c2b   = (const float*)d_in[11];
    const float* finw  = (const float*)d_in[12];
    const float* finb  = (const float*)d_in[13];
    float* out = (float*)d_out;

    conv_pre<<<1, 128>>>(c1w, c1b, c2w, c2b);
    zero_rc<<<(Bsz*Tn + 255) / 256, 256>>>();
    bmm_kernel<<<dim3(4, 2, Bsz), 256>>>(vis, txt);
    conv_kernel<<<dim3(8, 7, Bsz), dim3(64, 4)>>>(c2b);
    act_kernel<<<(Bsz*Tn + 255) / 256, 256>>>();
    cls_kernel<<<dim3(3, Bsz), 256>>>(vis, txt);
    fc_kernel<<<dim3(6, 128), 256>>>(txt, fc1w, fc1b);
    pred_kernel<<<Mfc / 8, 256>>>(fc2w, fc2b);
    loss1_kernel<<<Bsz, 512>>>(sent, lens);
    emb_kernel<<<dim3(Bsz, 2), 256>>>(fc1w, fc1b);
    tail1_kernel<<<1, 1024>>>(fc2w, fc2b);
    contrast_kernel<<<Bsz, 1024>>>();
    varsem_kernel<<<1, Dn>>>();
    final_kernel<<<Bsz, 256>>>(finw, finb, out);
    finalize_kernel<<<1, 32>>>(out, out_size);
}

// round 11
// speedup vs baseline: 1.5015x; 1.5015x over previous
#include <cuda_runtime.h>
#include <cuda_bf16.h>
#include <stdint.h>
#include <math.h>

#define Bsz 32
#define Vn 197
#define Tn 512
#define Dn 768
#define KP 2304          // packed K = 3 * Dn (hi/lo correction folded into K)
#define KC 32            // K-chunk per stage (bf16 elements)
#define NCH (KP/KC)      // 72 chunks

// ---------------- scratch (static device memory; no runtime allocs) ----------------
__device__ float g_S[Bsz*Vn*Tn];
__device__ float g_rowsum[Bsz*Vn];
__device__ float g_colsum[Bsz*Tn];
__device__ float g_vcls[Bsz*Dn];
__device__ float g_tcls[Bsz*Dn];
__device__ float g_vemb[Bsz*Dn];
__device__ float g_temb[Bsz*Dn];
__device__ float g_vhat[Bsz*Dn];
__device__ float g_that[Bsz*Dn];
__device__ float g_pred[Bsz*Tn];
__device__ float g_vs[Bsz], g_ts[Bsz], g_lam[Bsz], g_per[Bsz], g_rowloss[Bsz];
__device__ float g_A[81], g_Bq[9], g_K[25], g_C[1];
__device__ float g_nvarv[Dn], g_nvart[Dn];

// K-packed bf16 operands: A-style = [hi, lo, hi], B-style = [hi, hi, lo]
__device__ __align__(16) __nv_bfloat16 g_w1p [Dn*KP];        // B operand (fc)
__device__ __align__(16) __nv_bfloat16 g_txtA[Bsz*Tn*KP];    // A operand (fc)
__device__ __align__(16) __nv_bfloat16 g_txtB[Bsz*Tn*KP];    // B operand (bmm)
__device__ __align__(16) __nv_bfloat16 g_visA[Bsz*Vn*KP];    // A operand (bmm)

// ---------------- warp-MMA helpers (base sm_103: HMMA via mma.sync) ----------------
__device__ __forceinline__ uint32_t smem_u32(const void* p) {
    uint32_t a;
    asm("{ .reg .u64 t; cvta.to.shared.u64 t, %1; cvt.u32.u64 %0, t; }" : "=r"(a) : "l"(p));
    return a;
}
__device__ __forceinline__ void ldsm_x4(uint32_t* r, uint32_t addr) {
    asm volatile("ldmatrix.sync.aligned.m8n8.x4.shared.b16 {%0,%1,%2,%3}, [%4];"
        : "=r"(r[0]), "=r"(r[1]), "=r"(r[2]), "=r"(r[3]) : "r"(addr));
}
__device__ __forceinline__ void ldsm_x2(uint32_t* r, uint32_t addr) {
    asm volatile("ldmatrix.sync.aligned.m8n8.x2.shared.b16 {%0,%1}, [%2];"
        : "=r"(r[0]), "=r"(r[1]) : "r"(addr));
}
__device__ __forceinline__ void mma_bf16(float* d, const uint32_t* a, const uint32_t* b) {
    asm volatile("mma.sync.aligned.m16n8k16.row.col.f32.bf16.bf16.f32 "
        "{%0,%1,%2,%3}, {%4,%5,%6,%7}, {%8,%9}, {%0,%1,%2,%3};"
        : "+f"(d[0]), "+f"(d[1]), "+f"(d[2]), "+f"(d[3])
        : "r"(a[0]), "r"(a[1]), "r"(a[2]), "r"(a[3]), "r"(b[0]), "r"(b[1]));
}

// ---------------- conv composition precompute ----------------
__global__ void conv_pre(const float* __restrict__ w1, const float* __restrict__ b1,
                         const float* __restrict__ w2, const float* __restrict__ b2) {
    int t = threadIdx.x;
    if (t < 81) {
        int q = t / 9, s = t % 9;
        float a = 0.f;
        for (int c = 0; c < 64; c++) a += w2[c*9 + q] * w1[c*9 + s];
        g_A[t] = a;
    } else if (t < 90) {
        int q = t - 81;
        float a = 0.f;
        for (int c = 0; c < 64; c++) a += w2[c*9 + q] * b1[c];
        g_Bq[q] = a;
    }
    __syncthreads();
    if (t < 25) {
        int u = t / 5, w = t % 5;
        float a = 0.f;
        for (int qi = 0; qi < 3; qi++) for (int si = 0; si < 3; si++) if (qi + si == u)
            for (int qj = 0; qj < 3; qj++) for (int sj = 0; sj < 3; sj++) if (qj + sj == w)
                a += g_A[(qi*3 + qj)*9 + si*3 + sj];
        g_K[t] = a;
    }
    if (t == 127) {
        float a = b2[0];
        for (int q = 0; q < 9; q++) a += g_Bq[q];
        g_C[0] = a;
    }
}

__global__ void zero_rc() {
    int i = blockIdx.x * blockDim.x + threadIdx.x;
    if (i < Bsz*Vn) g_rowsum[i] = 0.f;
    if (i < Bsz*Tn) { g_colsum[i] = 0.f; g_pred[i] = 0.f; }
}

// ---------------- conversion: fp32 -> K-packed bf16 hi/lo ----------------
__global__ void cvt_w1(const float* __restrict__ x) {          // B-style
    int i = blockIdx.x * 256 + threadIdx.x;
    if (i < Dn*Dn) {
        int row = i / Dn, k = i % Dn;
        float v = x[i];
        __nv_bfloat16 h = __float2bfloat16(v);
        __nv_bfloat16 l = __float2bfloat16(v - __bfloat162float(h));
        size_t base = (size_t)row * KP;
        g_w1p[base + k] = h; g_w1p[base + Dn + k] = h; g_w1p[base + 2*Dn + k] = l;
    }
}
__global__ void cvt_txt(const float* __restrict__ x) {         // A-style + B-style
    int i = blockIdx.x * 256 + threadIdx.x;
    if (i < Bsz*Tn*Dn) {
        int row = i / Dn, k = i % Dn;
        float v = x[i];
        __nv_bfloat16 h = __float2bfloat16(v);
        __nv_bfloat16 l = __float2bfloat16(v - __bfloat162float(h));
        size_t base = (size_t)row * KP;
        g_txtA[base + k] = h; g_txtA[base + Dn + k] = l; g_txtA[base + 2*Dn + k] = h;
        g_txtB[base + k] = h; g_txtB[base + Dn + k] = h; g_txtB[base + 2*Dn + k] = l;
    }
}
__global__ void cvt_vis(const float* __restrict__ x) {         // A-style
    int i = blockIdx.x * 256 + threadIdx.x;
    if (i < Bsz*Vn*Dn) {
        int row = i / Dn, k = i % Dn;
        float v = x[i];
        __nv_bfloat16 h = __float2bfloat16(v);
        __nv_bfloat16 l = __float2bfloat16(v - __bfloat162float(h));
        size_t base = (size_t)row * KP;
        g_visA[base + k] = h; g_visA[base + Dn + k] = l; g_visA[base + 2*Dn + k] = h;
    }
}

// ---------------- warp-MMA GEMM: C = A @ B^T over packed K ----------------
// mode 0 (bmm): A=g_visA [197,KP]/b, B=g_txtB [512,KP]/b, C -> g_S
// mode 1 (fc) : A=g_txtA [16384,KP], B=g_w1p [768,KP],
//               epilogue: pred[m] += sum_n relu(ta[m]*C + b1[n]) * w2[n]
__global__ __launch_bounds__(256) void mma_gemm(int mode, const float* __restrict__ b1,
                                                const float* __restrict__ w2) {
    __shared__ __nv_bfloat16 As[128][40];
    __shared__ __nv_bfloat16 Bs[128][40];
    int tid = threadIdx.x, wid = tid >> 5, lane = tid & 31;
    int n0 = blockIdx.x * 128, m0 = blockIdx.y * 128, bz = blockIdx.z;

    const __nv_bfloat16 *Ap, *Bp;
    int mValid;
    if (mode == 0) {
        Ap = g_visA + (size_t)bz * Vn * KP;
        Bp = g_txtB + (size_t)bz * Tn * KP;
        mValid = Vn;
    } else {
        Ap = g_txtA;
        Bp = g_w1p;
        mValid = 1 << 30;
    }

    float acc[4][4][4];
#pragma unroll
    for (int i = 0; i < 4; i++)
#pragma unroll
        for (int j = 0; j < 4; j++)
#pragma unroll
            for (int k = 0; k < 4; k++) acc[i][j][k] = 0.f;

    int lr = tid >> 1;              // row 0..127
    int lk = (tid & 1) * 16;        // element offset 0 / 16
    bool aOK = (m0 + lr) < mValid;
    const __nv_bfloat16* aG = Ap + (size_t)(m0 + lr) * KP + lk;
    const __nv_bfloat16* bG = Bp + (size_t)(n0 + lr) * KP + lk;

    uint4 pa0, pa1, pb0, pb1;
    const uint4 z4 = make_uint4(0,0,0,0);
    pa0 = aOK ? *(const uint4*)(aG)     : z4;
    pa1 = aOK ? *(const uint4*)(aG + 8) : z4;
    pb0 = *(const uint4*)(bG);
    pb1 = *(const uint4*)(bG + 8);

    int warp_m = (wid & 1) * 64, warp_n = (wid >> 1) * 32;
    uint32_t aAddrBase[2], bAddrBase[2];
#pragma unroll
    for (int ks = 0; ks < 2; ks++) {
        aAddrBase[ks] = smem_u32(&As[warp_m + (lane & 15)][ks*16 + (lane >> 4) * 8]);
        bAddrBase[ks] = smem_u32(&Bs[warp_n + (lane & 7)][ks*16 + ((lane >> 3) & 1) * 8]);
    }

    for (int kc = 0; kc < NCH; kc++) {
        __syncthreads();
        *(uint4*)&As[lr][lk]     = pa0;
        *(uint4*)&As[lr][lk + 8] = pa1;
        *(uint4*)&Bs[lr][lk]     = pb0;
        *(uint4*)&Bs[lr][lk + 8] = pb1;
        __syncthreads();
        if (kc + 1 < NCH) {
            const __nv_bfloat16* an = aG + (kc + 1) * KC;
            const __nv_bfloat16* bn = bG + (kc + 1) * KC;
            pa0 = aOK ? *(const uint4*)(an)     : z4;
            pa1 = aOK ? *(const uint4*)(an + 8) : z4;
            pb0 = *(const uint4*)(bn);
            pb1 = *(const uint4*)(bn + 8);
        }
#pragma unroll
        for (int ks = 0; ks < 2; ks++) {
            uint32_t af[4][4], bf[4][2];
#pragma unroll
            for (int f = 0; f < 4; f++) ldsm_x4(af[f], aAddrBase[ks] + f * 16 * 80);
#pragma unroll
            for (int g = 0; g < 4; g++) ldsm_x2(bf[g], bAddrBase[ks] + g * 8 * 80);
#pragma unroll
            for (int f = 0; f < 4; f++)
#pragma unroll
                for (int g = 0; g < 4; g++) mma_bf16(acc[f][g], af[f], bf[g]);
        }
    }

    if (mode == 1) {
        // fused fc epilogue: pred[m] += sum_n relu(ta*C + b1)*w2 over this CTA's n-range
#pragma unroll
        for (int mf = 0; mf < 4; mf++) {
#pragma unroll
            for (int half = 0; half < 2; half++) {
                int m = m0 + warp_m + mf * 16 + (lane >> 2) + half * 8;
                float ta = g_colsum[m];
                float s = 0.f;
#pragma unroll
                for (int nf = 0; nf < 4; nf++) {
                    int n = n0 + warp_n + nf * 8 + (lane & 3) * 2;
                    float v0 = acc[mf][nf][half*2 + 0];
                    float v1 = acc[mf][nf][half*2 + 1];
                    s += fmaxf(ta * v0 + b1[n],     0.f) * w2[n];
                    s += fmaxf(ta * v1 + b1[n + 1], 0.f) * w2[n + 1];
                }
                s += __shfl_xor_sync(0xffffffffu, s, 1);
                s += __shfl_xor_sync(0xffffffffu, s, 2);
                if ((lane & 3) == 0) atomicAdd(&g_pred[m], s);
            }
        }
    } else {
        float* Cb = g_S + (size_t)bz * Vn * Tn;
#pragma unroll
        for (int mf = 0; mf < 4; mf++) {
            int m = m0 + warp_m + mf * 16 + (lane >> 2);
#pragma unroll
            for (int nf = 0; nf < 4; nf++) {
                int n = n0 + warp_n + nf * 8 + (lane & 3) * 2;
                if (m < Vn)
                    *(float2*)&Cb[(size_t)m * Tn + n] = make_float2(acc[mf][nf][0], acc[mf][nf][1]);
                if (m + 8 < Vn)
                    *(float2*)&Cb[(size_t)(m + 8) * Tn + n] = make_float2(acc[mf][nf][2], acc[mf][nf][3]);
            }
        }
    }
}

// ---------------- fused conv(5x5 eq) + relu + row/col reduce ----------------
__global__ void conv_kernel(const float* __restrict__ b2ptr) {
    int b = blockIdx.z;
    int v0 = blockIdx.y * 32, t0 = blockIdx.x * 64;
    __shared__ float sh[36][68];
    __shared__ float shA[81], shB[9], shK[25];
    __shared__ float shRow[32], shCol[64];
    int tid = threadIdx.y * 64 + threadIdx.x;
    if (tid < 81) shA[tid] = g_A[tid];
    if (tid < 9)  shB[tid] = g_Bq[tid];
    if (tid < 25) shK[tid] = g_K[tid];
    if (tid < 32) shRow[tid] = 0.f;
    if (tid < 64) shCol[tid] = 0.f;
    float cC  = g_C[0];
    float b2v = b2ptr[0];
    const float* Sb = g_S + (size_t)b * Vn * Tn;
    for (int i = tid; i < 36*68; i += 256) {
        int r = i / 68, c = i % 68;
        int gv = v0 - 2 + r, gt = t0 - 2 + c;
        sh[r][c] = (gv >= 0 && gv < Vn && gt >= 0 && gt < Tn) ? Sb[(size_t)gv * Tn + gt] : 0.f;
    }
    __syncthreads();
    int tx = threadIdx.x;
    float colAcc = 0.f;
#pragma unroll
    for (int kk = 0; kk < 8; kk++) {
        int vl = threadIdx.y + kk * 4;
        int gv = v0 + vl, gt = t0 + tx;
        float z = 0.f;
        if (gv < Vn) {
            if (gv >= 1 && gv <= Vn-2 && gt >= 1 && gt <= Tn-2) {
                z = cC;
#pragma unroll
                for (int u = 0; u < 5; u++)
#pragma unroll
                    for (int w = 0; w < 5; w++) z += shK[u*5 + w] * sh[vl + u][tx + w];
            } else {
                z = b2v;
#pragma unroll
                for (int qi = 0; qi < 3; qi++)
#pragma unroll
                    for (int qj = 0; qj < 3; qj++) {
                        int pv = gv + qi - 1, pt = gt + qj - 1;
                        if (pv >= 0 && pv < Vn && pt >= 0 && pt < Tn) {
                            int q = qi*3 + qj;
                            z += shB[q];
#pragma unroll
                            for (int si = 0; si < 3; si++)
#pragma unroll
                                for (int sj = 0; sj < 3; sj++)
                                    z += shA[q*9 + si*3 + sj] * sh[vl + qi + si][tx + qj + sj];
                        }
                    }
            }
            z = fmaxf(z, 0.f);
        }
        float r = z;
        for (int o = 16; o; o >>= 1) r += __shfl_down_sync(0xffffffffu, r, o);
        if ((tid & 31) == 0 && gv < Vn) atomicAdd(&shRow[vl], r);
        colAcc += z;
    }
    atomicAdd(&shCol[tx], colAcc);
    __syncthreads();
    if (tid < 32 && v0 + tid < Vn) atomicAdd(&g_rowsum[b*Vn + v0 + tid], shRow[tid]);
    if (tid < 64) atomicAdd(&g_colsum[b*Tn + t0 + tid], shCol[tid]);
}

// rowsum -> va = sigmoid(sum/T); colsum -> ta = sigmoid(sum/V)
__global__ void act_kernel() {
    int i = blockIdx.x * blockDim.x + threadIdx.x;
    if (i < Bsz*Vn) g_rowsum[i] = 1.f / (1.f + expf(-g_rowsum[i] / (float)Tn));
    if (i < Bsz*Tn) g_colsum[i] = 1.f / (1.f + expf(-g_colsum[i] / (float)Vn));
}

// CLS means (attention-weighted)
__global__ void cls_kernel(const float* __restrict__ vis, const float* __restrict__ txt) {
    int b = blockIdx.y;
    int d = blockIdx.x * 256 + threadIdx.x;
    float acc = 0.f;
    for (int v = 0; v < Vn; v++) acc += g_rowsum[b*Vn + v] * vis[((size_t)b*Vn + v)*Dn + d];
    g_vcls[b*Dn + d] = acc / (float)Vn;
    float acc2 = 0.f;
    for (int t = 0; t < Tn; t++) acc2 += g_colsum[b*Tn + t] * txt[((size_t)b*Tn + t)*Dn + d];
    g_tcls[b*Dn + d] = acc2 / (float)Tn;
}

// masked per-sample sentiment MSE (pred accumulated by fc epilogue; add fc2 bias here)
__global__ void loss1_kernel(const float* __restrict__ sent, const int* __restrict__ lens,
                             const float* __restrict__ b2) {
    int b = blockIdx.x, t = threadIdx.x;
    float s = sent[b*Tn + t];
    float p = g_pred[b*Tn + t] + b2[0];
    if (s == 0.f) p = 0.f;
    int len = lens[b];
    float e = 0.f;
    if (t < len) { float df = p - s; e = df * df; }
    __shared__ float red[512];
    red[t] = e; __syncthreads();
    for (int o = 256; o > 0; o >>= 1) { if (t < o) red[t] += red[t + o]; __syncthreads(); }
    if (t == 0) g_per[b] = red[0] / (float)len;
}

// small GEMMs: t_emb = tCLS@fc1^T + b, v_emb = vCLS@fc1^T + b
__global__ void emb_kernel(const float* __restrict__ w1, const float* __restrict__ b1) {
    int b = blockIdx.x;
    int which = blockIdx.y;
    const float* src = which ? g_vcls : g_tcls;
    float* dst = which ? g_vemb : g_temb;
    __shared__ float cls[Dn];
    int tid = threadIdx.x;
    for (int i = tid; i < Dn; i += 256) cls[i] = src[b*Dn + i];
    __syncthreads();
    for (int n = tid; n < Dn; n += 256) {
        const float4* wr = (const float4*)(w1 + (size_t)n * Dn);
        float acc = b1[n];
#pragma unroll 4
        for (int k4 = 0; k4 < Dn/4; k4++) {
            float4 w = wr[k4];
            acc += cls[k4*4+0]*w.x + cls[k4*4+1]*w.y + cls[k4*4+2]*w.z + cls[k4*4+3]*w.w;
        }
        dst[b*Dn + n] = acc;
    }
}

// v_s, t_s, lamda, normalized embeddings (one warp per batch row)
__global__ void tail1_kernel(const float* __restrict__ w2, const float* __restrict__ b2) {
    int b = threadIdx.x >> 5;
    int lane = threadIdx.x & 31;
    float sv = 0.f, st = 0.f, nv = 0.f, nt = 0.f;
    for (int d = lane; d < Dn; d += 32) {
        float ve = g_vemb[b*Dn + d], te = g_temb[b*Dn + d], wv = w2[d];
        sv += fmaxf(ve, 0.f) * wv;
        st += te * wv;
        nv += ve * ve; nt += te * te;
    }
    for (int o = 16; o; o >>= 1) {
        sv += __shfl_xor_sync(0xffffffffu, sv, o);
        st += __shfl_xor_sync(0xffffffffu, st, o);
        nv += __shfl_xor_sync(0xffffffffu, nv, o);
        nt += __shfl_xor_sync(0xffffffffu, nt, o);
    }
    float dnv = fmaxf(sqrtf(nv), 1e-12f), dnt = fmaxf(sqrtf(nt), 1e-12f);
    for (int d = lane; d < Dn; d += 32) {
        g_vhat[b*Dn + d] = g_vemb[b*Dn + d] / dnv;
        g_that[b*Dn + d] = g_temb[b*Dn + d] / dnt;
    }
    if (lane == 0) {
        float vs = sv + b2[0], ts = st + b2[0];
        g_vs[b] = vs; g_ts[b] = ts; g_lam[b] = fabsf(ts - vs);
    }
}

// per-row KL(contrast || sim)
__global__ void contrast_kernel() {
    int i = blockIdx.x;
    int w = threadIdx.x >> 5, lane = threadIdx.x & 31;
    __shared__ float shZ[32];
    float dot = 0.f;
    for (int d = lane; d < Dn; d += 32) dot += g_vhat[i*Dn + d] * g_that[w*Dn + d];
    for (int o = 16; o; o >>= 1) dot += __shfl_xor_sync(0xffffffffu, dot, o);
    if (lane == 0) shZ[w] = dot * 5.0f;   // /0.2
    __syncthreads();
    if (threadIdx.x < 32) {
        int j = threadIdx.x;
        float z = shZ[j];
        float cu = expf(-fabsf(g_vs[i] - g_ts[j]));
        float su = expf(z);
        float cs = cu, ss = su;
        for (int o = 16; o; o >>= 1) {
            cs += __shfl_xor_sync(0xffffffffu, cs, o);
            ss += __shfl_xor_sync(0xffffffffu, ss, o);
        }
        float c = cu / cs;
        float term = c * (logf(c) - (z - logf(ss)));
        for (int o = 16; o; o >>= 1) term += __shfl_xor_sync(0xffffffffu, term, o);
        if (j == 0) g_rowloss[i] = term;
    }
}

// per-dim variance over batch (ddof=1), l2-normalized over D
__global__ void varsem_kernel() {
    int d = threadIdx.x;  // 768 threads
    __shared__ float red[Dn];
    __shared__ float s_nv, s_nt;
    float mv = 0.f, mt = 0.f;
    for (int b = 0; b < Bsz; b++) { mv += g_vcls[b*Dn + d]; mt += g_tcls[b*Dn + d]; }
    mv /= 32.f; mt /= 32.f;
    float vv = 0.f, vt = 0.f;
    for (int b = 0; b < Bsz; b++) {
        float x = g_vcls[b*Dn + d] - mv; vv += x * x;
        float y = g_tcls[b*Dn + d] - mt; vt += y * y;
    }
    vv /= 31.f; vt /= 31.f;
    red[d] = vv * vv; __syncthreads();
    if (d < 256) red[d] += red[d + 512];
    __syncthreads();
    for (int s = 256; s > 0; s >>= 1) { if (d < s) red[d] += red[d + s]; __syncthreads(); }
    if (d == 0) s_nv = fmaxf(sqrtf(red[0]), 1e-12f);
    __syncthreads();
    red[d] = vt * vt; __syncthreads();
    if (d < 256) red[d] += red[d + 512];
    __syncthreads();
    for (int s = 256; s > 0; s >>= 1) { if (d < s) red[d] += red[d + s]; __syncthreads(); }
    if (d == 0) s_nt = fmaxf(sqrtf(red[0]), 1e-12f);
    __syncthreads();
    g_nvarv[d] = vv / s_nv;
    g_nvart[d] = vt / s_nt;
}

// final fused head -> out[0..31]
__global__ void final_kernel(const float* __restrict__ fw, const float* __restrict__ fb,
                             float* __restrict__ out) {
    int b = blockIdx.x;
    int tid = threadIdx.x;
    float acc = 0.f;
    for (int d = tid; d < Dn; d += 256) {
        float vc = g_vcls[b*Dn + d], tc = g_tcls[b*Dn + d];
        float sv = vc * (1.f + g_nvarv[d]);
        float st = tc * (1.f + g_nvart[d]);
        float f = 0.5f * (sv * st + g_vemb[b*Dn + d] * g_temb[b*Dn + d]);
        acc += f * fw[d];
    }
    __shared__ float red[256];
    red[tid] = acc; __syncthreads();
    for (int o = 128; o > 0; o >>= 1) { if (tid < o) red[tid] += red[tid + o]; __syncthreads(); }
    if (tid == 0) out[b] = red[0] + fb[0] + 0.1f * g_lam[b] - 0.5f;
}

__global__ void finalize_kernel(float* __restrict__ out, int out_size) {
    int t = threadIdx.x;  // 32
    float a = g_rowloss[t], p = g_per[t];
    for (int o = 16; o; o >>= 1) {
        a += __shfl_xor_sync(0xffffffffu, a, o);
        p += __shfl_xor_sync(0xffffffffu, p, o);
    }
    if (t == 0) { out[32] = a / 32.f; out[33] = p / 32.f; }
    for (int i = 34 + t; i < out_size; i += 32) out[i] = 0.f;
}

// ---------------- launch ----------------
extern "C" void kernel_launch(void* const* d_in, const int* in_sizes, int n_in,
                              void* d_out, int out_size) {
    const float* vis   = (const float*)d_in[0];
    const float* txt   = (const float*)d_in[1];
    const float* sent  = (const float*)d_in[2];
    const int*   lens  = (const int*)d_in[3];
    const float* fc1w  = (const float*)d_in[4];
    const float* fc1b  = (const float*)d_in[5];
    const float* fc2w  = (const float*)d_in[6];
    const float* fc2b  = (const float*)d_in[7];
    const float* c1w   = (const float*)d_in[8];
    const float* c1b   = (const float*)d_in[9];
    const float* c2w   = (const float*)d_in[10];
    const float* c2b   = (const float*)d_in[11];
    const float* finw  = (const float*)d_in[12];
    const float* finb  = (const float*)d_in[13];
    float* out = (float*)d_out;

    conv_pre<<<1, 128>>>(c1w, c1b, c2w, c2b);
    zero_rc<<<(Bsz*Tn + 255) / 256, 256>>>();
    cvt_w1 <<<(Dn*Dn + 255) / 256, 256>>>(fc1w);
    cvt_txt<<<(Bsz*Tn*Dn + 255) / 256, 256>>>(txt);
    cvt_vis<<<(Bsz*Vn*Dn + 255) / 256, 256>>>(vis);

    mma_gemm<<<dim3(4, 2, Bsz), 256>>>(0, nullptr, nullptr);   // bmm -> g_S
    conv_kernel<<<dim3(8, 7, Bsz), dim3(64, 4)>>>(c2b);
    act_kernel<<<(Bsz*Tn + 255) / 256, 256>>>();
    cls_kernel<<<dim3(3, Bsz), 256>>>(vis, txt);
    mma_gemm<<<dim3(6, 128, 1), 256>>>(1, fc1b, fc2w);         // fc -> g_pred
    loss1_kernel<<<Bsz, 512>>>(sent, lens, fc2b);
    emb_kernel<<<dim3(Bsz, 2), 256>>>(fc1w, fc1b);
    tail1_kernel<<<1, 1024>>>(fc2w, fc2b);
    contrast_kernel<<<Bsz, 1024>>>();
    varsem_kernel<<<1, Dn>>>();
    final_kernel<<<Bsz, 256>>>(finw, finb, out);
    finalize_kernel<<<1, 32>>>(out, out_size);
}

// round 16
// speedup vs baseline: 1.5870x; 1.0569x over previous
#include <cuda_runtime.h>
#include <cuda_bf16.h>
#include <stdint.h>
#include <math.h>

#define Bsz 32
#define Vn 197
#define Tn 512
#define Dn 768
#define KP 2304          // logical packed K = 3 * Dn (hi/lo correction folded into K)
#define KC 32            // K-chunk per stage (bf16 elements)
#define NCH (KP/KC)      // 72 chunks; 24 chunks per section

// ---------------- scratch (static device memory; no runtime allocs) ----------------
__device__ float g_S[Bsz*Vn*Tn];
__device__ float g_rowsum[Bsz*Vn];
__device__ float g_colsum[Bsz*Tn];
__device__ float g_vcls[Bsz*Dn];
__device__ float g_tcls[Bsz*Dn];
__device__ float g_vemb[Bsz*Dn];
__device__ float g_temb[Bsz*Dn];
__device__ float g_vhat[Bsz*Dn];
__device__ float g_that[Bsz*Dn];
__device__ float g_pred[Bsz*Tn];
__device__ float g_vs[Bsz], g_ts[Bsz], g_lam[Bsz], g_per[Bsz], g_rowloss[Bsz];
__device__ float g_A[81], g_Bq[9], g_K[25], g_C[1];
__device__ float g_nvarv[Dn], g_nvart[Dn];

// plain hi/lo bf16 planes (GEMM selects section per K-chunk)
__device__ __align__(16) __nv_bfloat16 g_w1h [Dn*Dn],      g_w1l [Dn*Dn];
__device__ __align__(16) __nv_bfloat16 g_txth[Bsz*Tn*Dn],  g_txtl[Bsz*Tn*Dn];
__device__ __align__(16) __nv_bfloat16 g_vish[Bsz*Vn*Dn],  g_visl[Bsz*Vn*Dn];

// ---------------- warp-MMA helpers (base sm_103: HMMA via mma.sync) ----------------
__device__ __forceinline__ uint32_t smem_u32(const void* p) {
    uint32_t a;
    asm("{ .reg .u64 t; cvta.to.shared.u64 t, %1; cvt.u32.u64 %0, t; }" : "=r"(a) : "l"(p));
    return a;
}
__device__ __forceinline__ void ldsm_x4(uint32_t* r, uint32_t addr) {
    asm volatile("ldmatrix.sync.aligned.m8n8.x4.shared.b16 {%0,%1,%2,%3}, [%4];"
        : "=r"(r[0]), "=r"(r[1]), "=r"(r[2]), "=r"(r[3]) : "r"(addr));
}
__device__ __forceinline__ void ldsm_x2(uint32_t* r, uint32_t addr) {
    asm volatile("ldmatrix.sync.aligned.m8n8.x2.shared.b16 {%0,%1}, [%2];"
        : "=r"(r[0]), "=r"(r[1]) : "r"(addr));
}
__device__ __forceinline__ void mma_bf16(float* d, const uint32_t* a, const uint32_t* b) {
    asm volatile("mma.sync.aligned.m16n8k16.row.col.f32.bf16.bf16.f32 "
        "{%0,%1,%2,%3}, {%4,%5,%6,%7}, {%8,%9}, {%0,%1,%2,%3};"
        : "+f"(d[0]), "+f"(d[1]), "+f"(d[2]), "+f"(d[3])
        : "r"(a[0]), "r"(a[1]), "r"(a[2]), "r"(a[3]), "r"(b[0]), "r"(b[1]));
}

// ---------------- conv composition precompute ----------------
__global__ void conv_pre(const float* __restrict__ w1, const float* __restrict__ b1,
                         const float* __restrict__ w2, const float* __restrict__ b2) {
    int t = threadIdx.x;
    if (t < 81) {
        int q = t / 9, s = t % 9;
        float a = 0.f;
        for (int c = 0; c < 64; c++) a += w2[c*9 + q] * w1[c*9 + s];
        g_A[t] = a;
    } else if (t < 90) {
        int q = t - 81;
        float a = 0.f;
        for (int c = 0; c < 64; c++) a += w2[c*9 + q] * b1[c];
        g_Bq[q] = a;
    }
    __syncthreads();
    if (t < 25) {
        int u = t / 5, w = t % 5;
        float a = 0.f;
        for (int qi = 0; qi < 3; qi++) for (int si = 0; si < 3; si++) if (qi + si == u)
            for (int qj = 0; qj < 3; qj++) for (int sj = 0; sj < 3; sj++) if (qj + sj == w)
                a += g_A[(qi*3 + qj)*9 + si*3 + sj];
        g_K[t] = a;
    }
    if (t == 127) {
        float a = b2[0];
        for (int q = 0; q < 9; q++) a += g_Bq[q];
        g_C[0] = a;
    }
}

__global__ void zero_rc() {
    int i = blockIdx.x * blockDim.x + threadIdx.x;
    if (i < Bsz*Vn) g_rowsum[i] = 0.f;
    if (i < Bsz*Tn) { g_colsum[i] = 0.f; g_pred[i] = 0.f; }
}

// ---------------- conversion: fp32 -> hi/lo planes, vectorized 4 elems/thread ----------------
__device__ __forceinline__ void cvt4(const float* __restrict__ x, __nv_bfloat16* __restrict__ h,
                                     __nv_bfloat16* __restrict__ l, int i4, int n) {
    if (i4 < n) {
        float4 v = *(const float4*)(x + i4);
        __nv_bfloat162 h01 = __floats2bfloat162_rn(v.x, v.y);
        __nv_bfloat162 h23 = __floats2bfloat162_rn(v.z, v.w);
        float2 hf01 = __bfloat1622float2(h01);
        float2 hf23 = __bfloat1622float2(h23);
        __nv_bfloat162 l01 = __floats2bfloat162_rn(v.x - hf01.x, v.y - hf01.y);
        __nv_bfloat162 l23 = __floats2bfloat162_rn(v.z - hf23.x, v.w - hf23.y);
        *(__nv_bfloat162*)(h + i4)     = h01;
        *(__nv_bfloat162*)(h + i4 + 2) = h23;
        *(__nv_bfloat162*)(l + i4)     = l01;
        *(__nv_bfloat162*)(l + i4 + 2) = l23;
    }
}
__global__ void cvt_w1(const float* __restrict__ x) {
    int i4 = (blockIdx.x * 256 + threadIdx.x) * 4;
    cvt4(x, g_w1h, g_w1l, i4, Dn*Dn);
}
__global__ void cvt_txt(const float* __restrict__ x) {
    int i4 = (blockIdx.x * 256 + threadIdx.x) * 4;
    cvt4(x, g_txth, g_txtl, i4, Bsz*Tn*Dn);
}
__global__ void cvt_vis(const float* __restrict__ x) {
    int i4 = (blockIdx.x * 256 + threadIdx.x) * 4;
    cvt4(x, g_vish, g_visl, i4, Bsz*Vn*Dn);
}

// ---------------- warp-MMA GEMM: C = A @ B^T over logical packed K ----------------
// A sections: [h | l | h], B sections: [h | h | l]  -> hh + lh + hl terms
// mode 0 (bmm): A=vis pairs [197,Dn]/b, B=txt pairs [512,Dn]/b, C -> g_S
// mode 1 (fc) : A=txt pairs [16384,Dn], B=w1 pairs [768,Dn],
//               epilogue: pred[m] += sum_n relu(ta[m]*C + b1[n]) * w2[n]
__global__ __launch_bounds__(256) void mma_gemm(int mode, const float* __restrict__ b1,
                                                const float* __restrict__ w2) {
    __shared__ __nv_bfloat16 As[128][40];
    __shared__ __nv_bfloat16 Bs[128][40];
    int tid = threadIdx.x, wid = tid >> 5, lane = tid & 31;
    int n0 = blockIdx.x * 128, m0 = blockIdx.y * 128, bz = blockIdx.z;

    const __nv_bfloat16 *Ah, *Al, *Bh, *Bl;
    int mValid;
    if (mode == 0) {
        Ah = g_vish + (size_t)bz * Vn * Dn;  Al = g_visl + (size_t)bz * Vn * Dn;
        Bh = g_txth + (size_t)bz * Tn * Dn;  Bl = g_txtl + (size_t)bz * Tn * Dn;
        mValid = Vn;
    } else {
        Ah = g_txth;  Al = g_txtl;
        Bh = g_w1h;   Bl = g_w1l;
        mValid = 1 << 30;
    }

    float acc[4][4][4];
#pragma unroll
    for (int i = 0; i < 4; i++)
#pragma unroll
        for (int j = 0; j < 4; j++)
#pragma unroll
            for (int k = 0; k < 4; k++) acc[i][j][k] = 0.f;

    int lr = tid >> 1;              // row 0..127
    int lk = (tid & 1) * 16;        // element offset 0 / 16
    bool aOK = (m0 + lr) < mValid;
    size_t aRow = (size_t)(m0 + lr) * Dn + lk;
    size_t bRow = (size_t)(n0 + lr) * Dn + lk;

    // per-chunk source: A sec l iff 24<=kc<48 ; B sec l iff kc>=48 ; col=(kc%24)*KC
    uint4 pa0, pa1, pb0, pb1;
    const uint4 z4 = make_uint4(0,0,0,0);
    {
        const __nv_bfloat16* a0 = Ah + aRow;      // kc=0: A h, col 0
        const __nv_bfloat16* b0 = Bh + bRow;      // kc=0: B h, col 0
        pa0 = aOK ? *(const uint4*)(a0)     : z4;
        pa1 = aOK ? *(const uint4*)(a0 + 8) : z4;
        pb0 = *(const uint4*)(b0);
        pb1 = *(const uint4*)(b0 + 8);
    }

    int warp_m = (wid & 1) * 64, warp_n = (wid >> 1) * 32;
    uint32_t aAddrBase[2], bAddrBase[2];
#pragma unroll
    for (int ks = 0; ks < 2; ks++) {
        aAddrBase[ks] = smem_u32(&As[warp_m + (lane & 15)][ks*16 + (lane >> 4) * 8]);
        bAddrBase[ks] = smem_u32(&Bs[warp_n + (lane & 7)][ks*16 + ((lane >> 3) & 1) * 8]);
    }

    for (int kc = 0; kc < NCH; kc++) {
        __syncthreads();
        *(uint4*)&As[lr][lk]     = pa0;
        *(uint4*)&As[lr][lk + 8] = pa1;
        *(uint4*)&Bs[lr][lk]     = pb0;
        *(uint4*)&Bs[lr][lk + 8] = pb1;
        __syncthreads();
        if (kc + 1 < NCH) {
            int kn = kc + 1;
            int col = (kn % 24) * KC;
            const __nv_bfloat16* an = ((kn >= 24 && kn < 48) ? Al : Ah) + aRow + col;
            const __nv_bfloat16* bn = ((kn >= 48) ? Bl : Bh) + bRow + col;
            pa0 = aOK ? *(const uint4*)(an)     : z4;
            pa1 = aOK ? *(const uint4*)(an + 8) : z4;
            pb0 = *(const uint4*)(bn);
            pb1 = *(const uint4*)(bn + 8);
        }
#pragma unroll
        for (int ks = 0; ks < 2; ks++) {
            uint32_t af[4][4], bf[4][2];
#pragma unroll
            for (int f = 0; f < 4; f++) ldsm_x4(af[f], aAddrBase[ks] + f * 16 * 80);
#pragma unroll
            for (int g = 0; g < 4; g++) ldsm_x2(bf[g], bAddrBase[ks] + g * 8 * 80);
#pragma unroll
            for (int f = 0; f < 4; f++)
#pragma unroll
                for (int g = 0; g < 4; g++) mma_bf16(acc[f][g], af[f], bf[g]);
        }
    }

    if (mode == 1) {
        // fused fc epilogue: pred[m] += sum_n relu(ta*C + b1)*w2 over this CTA's n-range
#pragma unroll
        for (int mf = 0; mf < 4; mf++) {
#pragma unroll
            for (int half = 0; half < 2; half++) {
                int m = m0 + warp_m + mf * 16 + (lane >> 2) + half * 8;
                float ta = g_colsum[m];
                float s = 0.f;
#pragma unroll
                for (int nf = 0; nf < 4; nf++) {
                    int n = n0 + warp_n + nf * 8 + (lane & 3) * 2;
                    float v0 = acc[mf][nf][half*2 + 0];
                    float v1 = acc[mf][nf][half*2 + 1];
                    s += fmaxf(ta * v0 + b1[n],     0.f) * w2[n];
                    s += fmaxf(ta * v1 + b1[n + 1], 0.f) * w2[n + 1];
                }
                s += __shfl_xor_sync(0xffffffffu, s, 1);
                s += __shfl_xor_sync(0xffffffffu, s, 2);
                if ((lane & 3) == 0) atomicAdd(&g_pred[m], s);
            }
        }
    } else {
        float* Cb = g_S + (size_t)bz * Vn * Tn;
#pragma unroll
        for (int mf = 0; mf < 4; mf++) {
            int m = m0 + warp_m + mf * 16 + (lane >> 2);
#pragma unroll
            for (int nf = 0; nf < 4; nf++) {
                int n = n0 + warp_n + nf * 8 + (lane & 3) * 2;
                if (m < Vn)
                    *(float2*)&Cb[(size_t)m * Tn + n] = make_float2(acc[mf][nf][0], acc[mf][nf][1]);
                if (m + 8 < Vn)
                    *(float2*)&Cb[(size_t)(m + 8) * Tn + n] = make_float2(acc[mf][nf][2], acc[mf][nf][3]);
            }
        }
    }
}

// ---------------- fused conv(5x5 eq) + relu + row/col reduce ----------------
__global__ void conv_kernel(const float* __restrict__ b2ptr) {
    int b = blockIdx.z;
    int v0 = blockIdx.y * 32, t0 = blockIdx.x * 64;
    __shared__ float sh[36][68];
    __shared__ float shA[81], shB[9], shK[25];
    __shared__ float shRow[32], shCol[64];
    int tid = threadIdx.y * 64 + threadIdx.x;
    if (tid < 81) shA[tid] = g_A[tid];
    if (tid < 9)  shB[tid] = g_Bq[tid];
    if (tid < 25) shK[tid] = g_K[tid];
    if (tid < 32) shRow[tid] = 0.f;
    if (tid < 64) shCol[tid] = 0.f;
    float cC  = g_C[0];
    float b2v = b2ptr[0];
    const float* Sb = g_S + (size_t)b * Vn * Tn;
    for (int i = tid; i < 36*68; i += 256) {
        int r = i / 68, c = i % 68;
        int gv = v0 - 2 + r, gt = t0 - 2 + c;
        sh[r][c] = (gv >= 0 && gv < Vn && gt >= 0 && gt < Tn) ? Sb[(size_t)gv * Tn + gt] : 0.f;
    }
    __syncthreads();
    int tx = threadIdx.x;
    float colAcc = 0.f;
#pragma unroll
    for (int kk = 0; kk < 8; kk++) {
        int vl = threadIdx.y + kk * 4;
        int gv = v0 + vl, gt = t0 + tx;
        float z = 0.f;
        if (gv < Vn) {
            if (gv >= 1 && gv <= Vn-2 && gt >= 1 && gt <= Tn-2) {
                z = cC;
#pragma unroll
                for (int u = 0; u < 5; u++)
#pragma unroll
                    for (int w = 0; w < 5; w++) z += shK[u*5 + w] * sh[vl + u][tx + w];
            } else {
                z = b2v;
#pragma unroll
                for (int qi = 0; qi < 3; qi++)
#pragma unroll
                    for (int qj = 0; qj < 3; qj++) {
                        int pv = gv + qi - 1, pt = gt + qj - 1;
                        if (pv >= 0 && pv < Vn && pt >= 0 && pt < Tn) {
                            int q = qi*3 + qj;
                            z += shB[q];
#pragma unroll
                            for (int si = 0; si < 3; si++)
#pragma unroll
                                for (int sj = 0; sj < 3; sj++)
                                    z += shA[q*9 + si*3 + sj] * sh[vl + qi + si][tx + qj + sj];
                        }
                    }
            }
            z = fmaxf(z, 0.f);
        }
        float r = z;
        for (int o = 16; o; o >>= 1) r += __shfl_down_sync(0xffffffffu, r, o);
        if ((tid & 31) == 0 && gv < Vn) atomicAdd(&shRow[vl], r);
        colAcc += z;
    }
    atomicAdd(&shCol[tx], colAcc);
    __syncthreads();
    if (tid < 32 && v0 + tid < Vn) atomicAdd(&g_rowsum[b*Vn + v0 + tid], shRow[tid]);
    if (tid < 64) atomicAdd(&g_colsum[b*Tn + t0 + tid], shCol[tid]);
}

// rowsum -> va = sigmoid(sum/T); colsum -> ta = sigmoid(sum/V)
__global__ void act_kernel() {
    int i = blockIdx.x * blockDim.x + threadIdx.x;
    if (i < Bsz*Vn) g_rowsum[i] = 1.f / (1.f + expf(-g_rowsum[i] / (float)Tn));
    if (i < Bsz*Tn) g_colsum[i] = 1.f / (1.f + expf(-g_colsum[i] / (float)Vn));
}

// CLS means (attention-weighted)
__global__ void cls_kernel(const float* __restrict__ vis, const float* __restrict__ txt) {
    int b = blockIdx.y;
    int d = blockIdx.x * 256 + threadIdx.x;
    float acc = 0.f;
    for (int v = 0; v < Vn; v++) acc += g_rowsum[b*Vn + v] * vis[((size_t)b*Vn + v)*Dn + d];
    g_vcls[b*Dn + d] = acc / (float)Vn;
    float acc2 = 0.f;
    for (int t = 0; t < Tn; t++) acc2 += g_colsum[b*Tn + t] * txt[((size_t)b*Tn + t)*Dn + d];
    g_tcls[b*Dn + d] = acc2 / (float)Tn;
}

// masked per-sample sentiment MSE (pred accumulated by fc epilogue; add fc2 bias here)
__global__ void loss1_kernel(const float* __restrict__ sent, const int* __restrict__ lens,
                             const float* __restrict__ b2) {
    int b = blockIdx.x, t = threadIdx.x;
    float s = sent[b*Tn + t];
    float p = g_pred[b*Tn + t] + b2[0];
    if (s == 0.f) p = 0.f;
    int len = lens[b];
    float e = 0.f;
    if (t < len) { float df = p - s; e = df * df; }
    __shared__ float red[512];
    red[t] = e; __syncthreads();
    for (int o = 256; o > 0; o >>= 1) { if (t < o) red[t] += red[t + o]; __syncthreads(); }
    if (t == 0) g_per[b] = red[0] / (float)len;
}

// small GEMMs: t_emb = tCLS@fc1^T + b, v_emb = vCLS@fc1^T + b
__global__ void emb_kernel(const float* __restrict__ w1, const float* __restrict__ b1) {
    int b = blockIdx.x;
    int which = blockIdx.y;
    const float* src = which ? g_vcls : g_tcls;
    float* dst = which ? g_vemb : g_temb;
    __shared__ float cls[Dn];
    int tid = threadIdx.x;
    for (int i = tid; i < Dn; i += 256) cls[i] = src[b*Dn + i];
    __syncthreads();
    for (int n = tid; n < Dn; n += 256) {
        const float4* wr = (const float4*)(w1 + (size_t)n * Dn);
        float acc = b1[n];
#pragma unroll 4
        for (int k4 = 0; k4 < Dn/4; k4++) {
            float4 w = wr[k4];
            acc += cls[k4*4+0]*w.x + cls[k4*4+1]*w.y + cls[k4*4+2]*w.z + cls[k4*4+3]*w.w;
        }
        dst[b*Dn + n] = acc;
    }
}

// v_s, t_s, lamda, normalized embeddings (one warp per batch row)
__global__ void tail1_kernel(const float* __restrict__ w2, const float* __restrict__ b2) {
    int b = threadIdx.x >> 5;
    int lane = threadIdx.x & 31;
    float sv = 0.f, st = 0.f, nv = 0.f, nt = 0.f;
    for (int d = lane; d < Dn; d += 32) {
        float ve = g_vemb[b*Dn + d], te = g_temb[b*Dn + d], wv = w2[d];
        sv += fmaxf(ve, 0.f) * wv;
        st += te * wv;
        nv += ve * ve; nt += te * te;
    }
    for (int o = 16; o; o >>= 1) {
        sv += __shfl_xor_sync(0xffffffffu, sv, o);
        st += __shfl_xor_sync(0xffffffffu, st, o);
        nv += __shfl_xor_sync(0xffffffffu, nv, o);
        nt += __shfl_xor_sync(0xffffffffu, nt, o);
    }
    float dnv = fmaxf(sqrtf(nv), 1e-12f), dnt = fmaxf(sqrtf(nt), 1e-12f);
    for (int d = lane; d < Dn; d += 32) {
        g_vhat[b*Dn + d] = g_vemb[b*Dn + d] / dnv;
        g_that[b*Dn + d] = g_temb[b*Dn + d] / dnt;
    }
    if (lane == 0) {
        float vs = sv + b2[0], ts = st + b2[0];
        g_vs[b] = vs; g_ts[b] = ts; g_lam[b] = fabsf(ts - vs);
    }
}

// per-row KL(contrast || sim)
__global__ void contrast_kernel() {
    int i = blockIdx.x;
    int w = threadIdx.x >> 5, lane = threadIdx.x & 31;
    __shared__ float shZ[32];
    float dot = 0.f;
    for (int d = lane; d < Dn; d += 32) dot += g_vhat[i*Dn + d] * g_that[w*Dn + d];
    for (int o = 16; o; o >>= 1) dot += __shfl_xor_sync(0xffffffffu, dot, o);
    if (lane == 0) shZ[w] = dot * 5.0f;   // /0.2
    __syncthreads();
    if (threadIdx.x < 32) {
        int j = threadIdx.x;
        float z = shZ[j];
        float cu = expf(-fabsf(g_vs[i] - g_ts[j]));
        float su = expf(z);
        float cs = cu, ss = su;
        for (int o = 16; o; o >>= 1) {
            cs += __shfl_xor_sync(0xffffffffu, cs, o);
            ss += __shfl_xor_sync(0xffffffffu, ss, o);
        }
        float c = cu / cs;
        float term = c * (logf(c) - (z - logf(ss)));
        for (int o = 16; o; o >>= 1) term += __shfl_xor_sync(0xffffffffu, term, o);
        if (j == 0) g_rowloss[i] = term;
    }
}

// per-dim variance over batch (ddof=1), l2-normalized over D
__global__ void varsem_kernel() {
    int d = threadIdx.x;  // 768 threads
    __shared__ float red[Dn];
    __shared__ float s_nv, s_nt;
    float mv = 0.f, mt = 0.f;
    for (int b = 0; b < Bsz; b++) { mv += g_vcls[b*Dn + d]; mt += g_tcls[b*Dn + d]; }
    mv /= 32.f; mt /= 32.f;
    float vv = 0.f, vt = 0.f;
    for (int b = 0; b < Bsz; b++) {
        float x = g_vcls[b*Dn + d] - mv; vv += x * x;
        float y = g_tcls[b*Dn + d] - mt; vt += y * y;
    }
    vv /= 31.f; vt /= 31.f;
    red[d] = vv * vv; __syncthreads();
    if (d < 256) red[d] += red[d + 512];
    __syncthreads();
    for (int s = 256; s > 0; s >>= 1) { if (d < s) red[d] += red[d + s]; __syncthreads(); }
    if (d == 0) s_nv = fmaxf(sqrtf(red[0]), 1e-12f);
    __syncthreads();
    red[d] = vt * vt; __syncthreads();
    if (d < 256) red[d] += red[d + 512];
    __syncthreads();
    for (int s = 256; s > 0; s >>= 1) { if (d < s) red[d] += red[d + s]; __syncthreads(); }
    if (d == 0) s_nt = fmaxf(sqrtf(red[0]), 1e-12f);
    __syncthreads();
    g_nvarv[d] = vv / s_nv;
    g_nvart[d] = vt / s_nt;
}

// final fused head -> out[0..31]
__global__ void final_kernel(const float* __restrict__ fw, const float* __restrict__ fb,
                             float* __restrict__ out) {
    int b = blockIdx.x;
    int tid = threadIdx.x;
    float acc = 0.f;
    for (int d = tid; d < Dn; d += 256) {
        float vc = g_vcls[b*Dn + d], tc = g_tcls[b*Dn + d];
        float sv = vc * (1.f + g_nvarv[d]);
        float st = tc * (1.f + g_nvart[d]);
        float f = 0.5f * (sv * st + g_vemb[b*Dn + d] * g_temb[b*Dn + d]);
        acc += f * fw[d];
    }
    __shared__ float red[256];
    red[tid] = acc; __syncthreads();
    for (int o = 128; o > 0; o >>= 1) { if (tid < o) red[tid] += red[tid + o]; __syncthreads(); }
    if (tid == 0) out[b] = red[0] + fb[0] + 0.1f * g_lam[b] - 0.5f;
}

__global__ void finalize_kernel(float* __restrict__ out, int out_size) {
    int t = threadIdx.x;  // 32
    float a = g_rowloss[t], p = g_per[t];
    for (int o = 16; o; o >>= 1) {
        a += __shfl_xor_sync(0xffffffffu, a, o);
        p += __shfl_xor_sync(0xffffffffu, p, o);
    }
    if (t == 0) { out[32] = a / 32.f; out[33] = p / 32.f; }
    for (int i = 34 + t; i < out_size; i += 32) out[i] = 0.f;
}

// ---------------- launch ----------------
extern "C" void kernel_launch(void* const* d_in, const int* in_sizes, int n_in,
                              void* d_out, int out_size) {
    const float* vis   = (const float*)d_in[0];
    const float* txt   = (const float*)d_in[1];
    const float* sent  = (const float*)d_in[2];
    const int*   lens  = (const int*)d_in[3];
    const float* fc1w  = (const float*)d_in[4];
    const float* fc1b  = (const float*)d_in[5];
    const float* fc2w  = (const float*)d_in[6];
    const float* fc2b  = (const float*)d_in[7];
    const float* c1w   = (const float*)d_in[8];
    const float* c1b   = (const float*)d_in[9];
    const float* c2w   = (const float*)d_in[10];
    const float* c2b   = (const float*)d_in[11];
    const float* finw  = (const float*)d_in[12];
    const float* finb  = (const float*)d_in[13];
    float* out = (float*)d_out;

    conv_pre<<<1, 128>>>(c1w, c1b, c2w, c2b);
    zero_rc<<<(Bsz*Tn + 255) / 256, 256>>>();
    cvt_w1 <<<(Dn*Dn/4 + 255) / 256, 256>>>(fc1w);
    cvt_txt<<<(Bsz*Tn*Dn/4 + 255) / 256, 256>>>(txt);
    cvt_vis<<<(Bsz*Vn*Dn/4 + 255) / 256, 256>>>(vis);

    mma_gemm<<<dim3(4, 2, Bsz), 256>>>(0, nullptr, nullptr);   // bmm -> g_S
    conv_kernel<<<dim3(8, 7, Bsz), dim3(64, 4)>>>(c2b);
    act_kernel<<<(Bsz*Tn + 255) / 256, 256>>>();
    cls_kernel<<<dim3(3, Bsz), 256>>>(vis, txt);
    mma_gemm<<<dim3(6, 128, 1), 256>>>(1, fc1b, fc2w);         // fc -> g_pred
    loss1_kernel<<<Bsz, 512>>>(sent, lens, fc2b);
    emb_kernel<<<dim3(Bsz, 2), 256>>>(fc1w, fc1b);
    tail1_kernel<<<1, 1024>>>(fc2w, fc2b);
    contrast_kernel<<<Bsz, 1024>>>();
    varsem_kernel<<<1, Dn>>>();
    final_kernel<<<Bsz, 256>>>(finw, finb, out);
    finalize_kernel<<<1, 32>>>(out, out_size);
}

// round 17
// speedup vs baseline: 1.6281x; 1.0259x over previous
#include <cuda_runtime.h>
#include <cuda_bf16.h>
#include <stdint.h>
#include <math.h>

#define Bsz 32
#define Vn 197
#define Tn 512
#define Dn 768
#define KP 2304          // logical packed K = 3 * Dn (hi/lo correction folded into K)
#define KC 32            // K-chunk per stage (bf16 elements)
#define NCH (KP/KC)      // 72 chunks; 24 chunks per section

// ---------------- scratch (static device memory; no runtime allocs) ----------------
__device__ float g_S[Bsz*Vn*Tn];
__device__ float g_rowsum[Bsz*Vn];
__device__ float g_colsum[Bsz*Tn];
__device__ float g_vcls[Bsz*Dn];
__device__ float g_tcls[Bsz*Dn];
__device__ float g_vemb[Bsz*Dn];
__device__ float g_temb[Bsz*Dn];
__device__ float g_vhat[Bsz*Dn];
__device__ float g_that[Bsz*Dn];
__device__ float g_pred[Bsz*Tn];
__device__ float g_vs[Bsz], g_ts[Bsz], g_lam[Bsz], g_per[Bsz], g_rowloss[Bsz];
__device__ float g_A[81], g_Bq[9], g_K[25], g_C[1];
__device__ float g_nvarv[Dn], g_nvart[Dn];

// plain hi/lo bf16 planes (GEMM selects section per K-chunk)
__device__ __align__(16) __nv_bfloat16 g_w1h [Dn*Dn],      g_w1l [Dn*Dn];
__device__ __align__(16) __nv_bfloat16 g_txth[Bsz*Tn*Dn],  g_txtl[Bsz*Tn*Dn];
__device__ __align__(16) __nv_bfloat16 g_vish[Bsz*Vn*Dn],  g_visl[Bsz*Vn*Dn];

// ---------------- warp-MMA helpers (base sm_103: HMMA via mma.sync) ----------------
__device__ __forceinline__ uint32_t smem_u32(const void* p) {
    uint32_t a;
    asm("{ .reg .u64 t; cvta.to.shared.u64 t, %1; cvt.u32.u64 %0, t; }" : "=r"(a) : "l"(p));
    return a;
}
__device__ __forceinline__ void ldsm_x4(uint32_t* r, uint32_t addr) {
    asm volatile("ldmatrix.sync.aligned.m8n8.x4.shared.b16 {%0,%1,%2,%3}, [%4];"
        : "=r"(r[0]), "=r"(r[1]), "=r"(r[2]), "=r"(r[3]) : "r"(addr));
}
__device__ __forceinline__ void ldsm_x2(uint32_t* r, uint32_t addr) {
    asm volatile("ldmatrix.sync.aligned.m8n8.x2.shared.b16 {%0,%1}, [%2];"
        : "=r"(r[0]), "=r"(r[1]) : "r"(addr));
}
__device__ __forceinline__ void mma_bf16(float* d, const uint32_t* a, const uint32_t* b) {
    asm volatile("mma.sync.aligned.m16n8k16.row.col.f32.bf16.bf16.f32 "
        "{%0,%1,%2,%3}, {%4,%5,%6,%7}, {%8,%9}, {%0,%1,%2,%3};"
        : "+f"(d[0]), "+f"(d[1]), "+f"(d[2]), "+f"(d[3])
        : "r"(a[0]), "r"(a[1]), "r"(a[2]), "r"(a[3]), "r"(b[0]), "r"(b[1]));
}
// cp.async 16B with ignore-src zfill when sz==0
#define CP16(dst, src, sz) \
    asm volatile("cp.async.cg.shared.global [%0], [%1], 16, %2;" \
        :: "r"(dst), "l"(src), "r"(sz) : "memory")
#define CP_COMMIT() asm volatile("cp.async.commit_group;" ::: "memory")
#define CP_WAIT1()  asm volatile("cp.async.wait_group 1;" ::: "memory")
#define CP_WAIT0()  asm volatile("cp.async.wait_group 0;" ::: "memory")

// ---------------- conv composition precompute ----------------
__global__ void conv_pre(const float* __restrict__ w1, const float* __restrict__ b1,
                         const float* __restrict__ w2, const float* __restrict__ b2) {
    int t = threadIdx.x;
    if (t < 81) {
        int q = t / 9, s = t % 9;
        float a = 0.f;
        for (int c = 0; c < 64; c++) a += w2[c*9 + q] * w1[c*9 + s];
        g_A[t] = a;
    } else if (t < 90) {
        int q = t - 81;
        float a = 0.f;
        for (int c = 0; c < 64; c++) a += w2[c*9 + q] * b1[c];
        g_Bq[q] = a;
    }
    __syncthreads();
    if (t < 25) {
        int u = t / 5, w = t % 5;
        float a = 0.f;
        for (int qi = 0; qi < 3; qi++) for (int si = 0; si < 3; si++) if (qi + si == u)
            for (int qj = 0; qj < 3; qj++) for (int sj = 0; sj < 3; sj++) if (qj + sj == w)
                a += g_A[(qi*3 + qj)*9 + si*3 + sj];
        g_K[t] = a;
    }
    if (t == 127) {
        float a = b2[0];
        for (int q = 0; q < 9; q++) a += g_Bq[q];
        g_C[0] = a;
    }
}

__global__ void zero_rc() {
    int i = blockIdx.x * blockDim.x + threadIdx.x;
    if (i < Bsz*Vn) g_rowsum[i] = 0.f;
    if (i < Bsz*Tn) { g_colsum[i] = 0.f; g_pred[i] = 0.f; }
}

// ---------------- conversion: fp32 -> hi/lo planes, vectorized 4 elems/thread ----------------
__device__ __forceinline__ void cvt4(const float* __restrict__ x, __nv_bfloat16* __restrict__ h,
                                     __nv_bfloat16* __restrict__ l, int i4, int n) {
    if (i4 < n) {
        float4 v = *(const float4*)(x + i4);
        __nv_bfloat162 h01 = __floats2bfloat162_rn(v.x, v.y);
        __nv_bfloat162 h23 = __floats2bfloat162_rn(v.z, v.w);
        float2 hf01 = __bfloat1622float2(h01);
        float2 hf23 = __bfloat1622float2(h23);
        __nv_bfloat162 l01 = __floats2bfloat162_rn(v.x - hf01.x, v.y - hf01.y);
        __nv_bfloat162 l23 = __floats2bfloat162_rn(v.z - hf23.x, v.w - hf23.y);
        *(__nv_bfloat162*)(h + i4)     = h01;
        *(__nv_bfloat162*)(h + i4 + 2) = h23;
        *(__nv_bfloat162*)(l + i4)     = l01;
        *(__nv_bfloat162*)(l + i4 + 2) = l23;
    }
}
__global__ void cvt_w1(const float* __restrict__ x) {
    int i4 = (blockIdx.x * 256 + threadIdx.x) * 4;
    cvt4(x, g_w1h, g_w1l, i4, Dn*Dn);
}
__global__ void cvt_txt(const float* __restrict__ x) {
    int i4 = (blockIdx.x * 256 + threadIdx.x) * 4;
    cvt4(x, g_txth, g_txtl, i4, Bsz*Tn*Dn);
}
__global__ void cvt_vis(const float* __restrict__ x) {
    int i4 = (blockIdx.x * 256 + threadIdx.x) * 4;
    cvt4(x, g_vish, g_visl, i4, Bsz*Vn*Dn);
}

// ---------------- warp-MMA GEMM with cp.async double-buffered smem ----------------
// A sections: [h | l | h], B sections: [h | h | l]  -> hh + lh + hl terms
// mode 0 (bmm): A=vis pairs [197,Dn]/b, B=txt pairs [512,Dn]/b, C -> g_S
// mode 1 (fc) : A=txt pairs [16384,Dn], B=w1 pairs [768,Dn],
//               epilogue: pred[m] += sum_n relu(ta[m]*C + b1[n]) * w2[n]
__global__ __launch_bounds__(256) void mma_gemm(int mode, const float* __restrict__ b1,
                                                const float* __restrict__ w2) {
    __shared__ __nv_bfloat16 As[2][128][40];
    __shared__ __nv_bfloat16 Bs[2][128][40];
    int tid = threadIdx.x, wid = tid >> 5, lane = tid & 31;
    int n0 = blockIdx.x * 128, m0 = blockIdx.y * 128, bz = blockIdx.z;

    const __nv_bfloat16 *Ah, *Al, *Bh, *Bl;
    int mValid;
    if (mode == 0) {
        Ah = g_vish + (size_t)bz * Vn * Dn;  Al = g_visl + (size_t)bz * Vn * Dn;
        Bh = g_txth + (size_t)bz * Tn * Dn;  Bl = g_txtl + (size_t)bz * Tn * Dn;
        mValid = Vn;
    } else {
        Ah = g_txth;  Al = g_txtl;
        Bh = g_w1h;   Bl = g_w1l;
        mValid = 1 << 30;
    }

    float acc[4][4][4];
#pragma unroll
    for (int i = 0; i < 4; i++)
#pragma unroll
        for (int j = 0; j < 4; j++)
#pragma unroll
            for (int k = 0; k < 4; k++) acc[i][j][k] = 0.f;

    int lr = tid >> 1;              // row 0..127
    int lk = (tid & 1) * 16;        // element offset 0 / 16
    bool aOK = (m0 + lr) < mValid;
    uint32_t asz = aOK ? 16u : 0u;  // zfill for invalid A rows
    size_t aRow = (size_t)(m0 + lr) * Dn + lk;
    size_t bRow = (size_t)(n0 + lr) * Dn + lk;

    uint32_t dstA[2], dstB[2];
#pragma unroll
    for (int b = 0; b < 2; b++) {
        dstA[b] = smem_u32(&As[b][lr][lk]);
        dstB[b] = smem_u32(&Bs[b][lr][lk]);
    }

    // issue cp.async for chunk kn into buffer buf
    auto issue = [&](int kn, int buf) {
        int col = (kn % 24) * KC;
        const __nv_bfloat16* an = ((kn >= 24 && kn < 48) ? Al : Ah) + aRow + col;
        const __nv_bfloat16* bn = ((kn >= 48) ? Bl : Bh) + bRow + col;
        CP16(dstA[buf],      an,     asz);
        CP16(dstA[buf] + 16, an + 8, asz);
        CP16(dstB[buf],      bn,     16u);
        CP16(dstB[buf] + 16, bn + 8, 16u);
    };

    int warp_m = (wid & 1) * 64, warp_n = (wid >> 1) * 32;
    uint32_t aAddr[2][2], bAddr[2][2];
#pragma unroll
    for (int b = 0; b < 2; b++)
#pragma unroll
        for (int ks = 0; ks < 2; ks++) {
            aAddr[b][ks] = smem_u32(&As[b][warp_m + (lane & 15)][ks*16 + (lane >> 4) * 8]);
            bAddr[b][ks] = smem_u32(&Bs[b][warp_n + (lane & 7)][ks*16 + ((lane >> 3) & 1) * 8]);
        }

    issue(0, 0);
    CP_COMMIT();
    for (int kc = 0; kc < NCH; kc++) {
        int buf = kc & 1;
        if (kc + 1 < NCH) {
            issue(kc + 1, buf ^ 1);
            CP_COMMIT();
            CP_WAIT1();
        } else {
            CP_WAIT0();
        }
        __syncthreads();
#pragma unroll
        for (int ks = 0; ks < 2; ks++) {
            uint32_t af[4][4], bf[4][2];
#pragma unroll
            for (int f = 0; f < 4; f++) ldsm_x4(af[f], aAddr[buf][ks] + f * 16 * 80);
#pragma unroll
            for (int g = 0; g < 4; g++) ldsm_x2(bf[g], bAddr[buf][ks] + g * 8 * 80);
#pragma unroll
            for (int f = 0; f < 4; f++)
#pragma unroll
                for (int g = 0; g < 4; g++) mma_bf16(acc[f][g], af[f], bf[g]);
        }
        __syncthreads();
    }

    if (mode == 1) {
        // fused fc epilogue: pred[m] += sum_n relu(ta*C + b1)*w2 over this CTA's n-range
#pragma unroll
        for (int mf = 0; mf < 4; mf++) {
#pragma unroll
            for (int half = 0; half < 2; half++) {
                int m = m0 + warp_m + mf * 16 + (lane >> 2) + half * 8;
                float ta = g_colsum[m];
                float s = 0.f;
#pragma unroll
                for (int nf = 0; nf < 4; nf++) {
                    int n = n0 + warp_n + nf * 8 + (lane & 3) * 2;
                    float v0 = acc[mf][nf][half*2 + 0];
                    float v1 = acc[mf][nf][half*2 + 1];
                    s += fmaxf(ta * v0 + b1[n],     0.f) * w2[n];
                    s += fmaxf(ta * v1 + b1[n + 1], 0.f) * w2[n + 1];
                }
                s += __shfl_xor_sync(0xffffffffu, s, 1);
                s += __shfl_xor_sync(0xffffffffu, s, 2);
                if ((lane & 3) == 0) atomicAdd(&g_pred[m], s);
            }
        }
    } else {
        float* Cb = g_S + (size_t)bz * Vn * Tn;
#pragma unroll
        for (int mf = 0; mf < 4; mf++) {
            int m = m0 + warp_m + mf * 16 + (lane >> 2);
#pragma unroll
            for (int nf = 0; nf < 4; nf++) {
                int n = n0 + warp_n + nf * 8 + (lane & 3) * 2;
                if (m < Vn)
                    *(float2*)&Cb[(size_t)m * Tn + n] = make_float2(acc[mf][nf][0], acc[mf][nf][1]);
                if (m + 8 < Vn)
                    *(float2*)&Cb[(size_t)(m + 8) * Tn + n] = make_float2(acc[mf][nf][2], acc[mf][nf][3]);
            }
        }
    }
}

// ---------------- fused conv(5x5 eq) + relu + row/col reduce ----------------
__global__ void conv_kernel(const float* __restrict__ b2ptr) {
    int b = blockIdx.z;
    int v0 = blockIdx.y * 32, t0 = blockIdx.x * 64;
    __shared__ float sh[36][68];
    __shared__ float shA[81], shB[9], shK[25];
    __shared__ float shRow[32], shCol[64];
    int tid = threadIdx.y * 64 + threadIdx.x;
    if (tid < 81) shA[tid] = g_A[tid];
    if (tid < 9)  shB[tid] = g_Bq[tid];
    if (tid < 25) shK[tid] = g_K[tid];
    if (tid < 32) shRow[tid] = 0.f;
    if (tid < 64) shCol[tid] = 0.f;
    float cC  = g_C[0];
    float b2v = b2ptr[0];
    const float* Sb = g_S + (size_t)b * Vn * Tn;
    for (int i = tid; i < 36*68; i += 256) {
        int r = i / 68, c = i % 68;
        int gv = v0 - 2 + r, gt = t0 - 2 + c;
        sh[r][c] = (gv >= 0 && gv < Vn && gt >= 0 && gt < Tn) ? Sb[(size_t)gv * Tn + gt] : 0.f;
    }
    __syncthreads();
    int tx = threadIdx.x;
    float colAcc = 0.f;
#pragma unroll
    for (int kk = 0; kk < 8; kk++) {
        int vl = threadIdx.y + kk * 4;
        int gv = v0 + vl, gt = t0 + tx;
        float z = 0.f;
        if (gv < Vn) {
            if (gv >= 1 && gv <= Vn-2 && gt >= 1 && gt <= Tn-2) {
                z = cC;
#pragma unroll
                for (int u = 0; u < 5; u++)
#pragma unroll
                    for (int w = 0; w < 5; w++) z += shK[u*5 + w] * sh[vl + u][tx + w];
            } else {
                z = b2v;
#pragma unroll
                for (int qi = 0; qi < 3; qi++)
#pragma unroll
                    for (int qj = 0; qj < 3; qj++) {
                        int pv = gv + qi - 1, pt = gt + qj - 1;
                        if (pv >= 0 && pv < Vn && pt >= 0 && pt < Tn) {
                            int q = qi*3 + qj;
                            z += shB[q];
#pragma unroll
                            for (int si = 0; si < 3; si++)
#pragma unroll
                                for (int sj = 0; sj < 3; sj++)
                                    z += shA[q*9 + si*3 + sj] * sh[vl + qi + si][tx + qj + sj];
                        }
                    }
            }
            z = fmaxf(z, 0.f);
        }
        float r = z;
        for (int o = 16; o; o >>= 1) r += __shfl_down_sync(0xffffffffu, r, o);
        if ((tid & 31) == 0 && gv < Vn) atomicAdd(&shRow[vl], r);
        colAcc += z;
    }
    atomicAdd(&shCol[tx], colAcc);
    __syncthreads();
    if (tid < 32 && v0 + tid < Vn) atomicAdd(&g_rowsum[b*Vn + v0 + tid], shRow[tid]);
    if (tid < 64) atomicAdd(&g_colsum[b*Tn + t0 + tid], shCol[tid]);
}

// rowsum -> va = sigmoid(sum/T); colsum -> ta = sigmoid(sum/V)
__global__ void act_kernel() {
    int i = blockIdx.x * blockDim.x + threadIdx.x;
    if (i < Bsz*Vn) g_rowsum[i] = 1.f / (1.f + expf(-g_rowsum[i] / (float)Tn));
    if (i < Bsz*Tn) g_colsum[i] = 1.f / (1.f + expf(-g_colsum[i] / (float)Vn));
}

// CLS means (attention-weighted)
__global__ void cls_kernel(const float* __restrict__ vis, const float* __restrict__ txt) {
    int b = blockIdx.y;
    int d = blockIdx.x * 256 + threadIdx.x;
    float acc = 0.f;
    for (int v = 0; v < Vn; v++) acc += g_rowsum[b*Vn + v] * vis[((size_t)b*Vn + v)*Dn + d];
    g_vcls[b*Dn + d] = acc / (float)Vn;
    float acc2 = 0.f;
    for (int t = 0; t < Tn; t++) acc2 += g_colsum[b*Tn + t] * txt[((size_t)b*Tn + t)*Dn + d];
    g_tcls[b*Dn + d] = acc2 / (float)Tn;
}

// masked per-sample sentiment MSE (pred accumulated by fc epilogue; add fc2 bias here)
__global__ void loss1_kernel(const float* __restrict__ sent, const int* __restrict__ lens,
                             const float* __restrict__ b2) {
    int b = blockIdx.x, t = threadIdx.x;
    float s = sent[b*Tn + t];
    float p = g_pred[b*Tn + t] + b2[0];
    if (s == 0.f) p = 0.f;
    int len = lens[b];
    float e = 0.f;
    if (t < len) { float df = p - s; e = df * df; }
    __shared__ float red[512];
    red[t] = e; __syncthreads();
    for (int o = 256; o > 0; o >>= 1) { if (t < o) red[t] += red[t + o]; __syncthreads(); }
    if (t == 0) g_per[b] = red[0] / (float)len;
}

// small GEMMs: t_emb = tCLS@fc1^T + b, v_emb = vCLS@fc1^T + b
__global__ void emb_kernel(const float* __restrict__ w1, const float* __restrict__ b1) {
    int b = blockIdx.x;
    int which = blockIdx.y;
    const float* src = which ? g_vcls : g_tcls;
    float* dst = which ? g_vemb : g_temb;
    __shared__ float cls[Dn];
    int tid = threadIdx.x;
    for (int i = tid; i < Dn; i += 256) cls[i] = src[b*Dn + i];
    __syncthreads();
    for (int n = tid; n < Dn; n += 256) {
        const float4* wr = (const float4*)(w1 + (size_t)n * Dn);
        float acc = b1[n];
#pragma unroll 4
        for (int k4 = 0; k4 < Dn/4; k4++) {
            float4 w = wr[k4];
            acc += cls[k4*4+0]*w.x + cls[k4*4+1]*w.y + cls[k4*4+2]*w.z + cls[k4*4+3]*w.w;
        }
        dst[b*Dn + n] = acc;
    }
}

// v_s, t_s, lamda, normalized embeddings (one warp per batch row)
__global__ void tail1_kernel(const float* __restrict__ w2, const float* __restrict__ b2) {
    int b = threadIdx.x >> 5;
    int lane = threadIdx.x & 31;
    float sv = 0.f, st = 0.f, nv = 0.f, nt = 0.f;
    for (int d = lane; d < Dn; d += 32) {
        float ve = g_vemb[b*Dn + d], te = g_temb[b*Dn + d], wv = w2[d];
        sv += fmaxf(ve, 0.f) * wv;
        st += te * wv;
        nv += ve * ve; nt += te * te;
    }
    for (int o = 16; o; o >>= 1) {
        sv += __shfl_xor_sync(0xffffffffu, sv, o);
        st += __shfl_xor_sync(0xffffffffu, st, o);
        nv += __shfl_xor_sync(0xffffffffu, nv, o);
        nt += __shfl_xor_sync(0xffffffffu, nt, o);
    }
    float dnv = fmaxf(sqrtf(nv), 1e-12f), dnt = fmaxf(sqrtf(nt), 1e-12f);
    for (int d = lane; d < Dn; d += 32) {
        g_vhat[b*Dn + d] = g_vemb[b*Dn + d] / dnv;
        g_that[b*Dn + d] = g_temb[b*Dn + d] / dnt;
    }
    if (lane == 0) {
        float vs = sv + b2[0], ts = st + b2[0];
        g_vs[b] = vs; g_ts[b] = ts; g_lam[b] = fabsf(ts - vs);
    }
}

// per-row KL(contrast || sim)
__global__ void contrast_kernel() {
    int i = blockIdx.x;
    int w = threadIdx.x >> 5, lane = threadIdx.x & 31;
    __shared__ float shZ[32];
    float dot = 0.f;
    for (int d = lane; d < Dn; d += 32) dot += g_vhat[i*Dn + d] * g_that[w*Dn + d];
    for (int o = 16; o; o >>= 1) dot += __shfl_xor_sync(0xffffffffu, dot, o);
    if (lane == 0) shZ[w] = dot * 5.0f;   // /0.2
    __syncthreads();
    if (threadIdx.x < 32) {
        int j = threadIdx.x;
        float z = shZ[j];
        float cu = expf(-fabsf(g_vs[i] - g_ts[j]));
        float su = expf(z);
        float cs = cu, ss = su;
        for (int o = 16; o; o >>= 1) {
            cs += __shfl_xor_sync(0xffffffffu, cs, o);
            ss += __shfl_xor_sync(0xffffffffu, ss, o);
        }
        float c = cu / cs;
        float term = c * (logf(c) - (z - logf(ss)));
        for (int o = 16; o; o >>= 1) term += __shfl_xor_sync(0xffffffffu, term, o);
        if (j == 0) g_rowloss[i] = term;
    }
}

// per-dim variance over batch (ddof=1), l2-normalized over D
__global__ void varsem_kernel() {
    int d = threadIdx.x;  // 768 threads
    __shared__ float red[Dn];
    __shared__ float s_nv, s_nt;
    float mv = 0.f, mt = 0.f;
    for (int b = 0; b < Bsz; b++) { mv += g_vcls[b*Dn + d]; mt += g_tcls[b*Dn + d]; }
    mv /= 32.f; mt /= 32.f;
    float vv = 0.f, vt = 0.f;
    for (int b = 0; b < Bsz; b++) {
        float x = g_vcls[b*Dn + d] - mv; vv += x * x;
        float y = g_tcls[b*Dn + d] - mt; vt += y * y;
    }
    vv /= 31.f; vt /= 31.f;
    red[d] = vv * vv; __syncthreads();
    if (d < 256) red[d] += red[d + 512];
    __syncthreads();
    for (int s = 256; s > 0; s >>= 1) { if (d < s) red[d] += red[d + s]; __syncthreads(); }
    if (d == 0) s_nv = fmaxf(sqrtf(red[0]), 1e-12f);
    __syncthreads();
    red[d] = vt * vt; __syncthreads();
    if (d < 256) red[d] += red[d + 512];
    __syncthreads();
    for (int s = 256; s > 0; s >>= 1) { if (d < s) red[d] += red[d + s]; __syncthreads(); }
    if (d == 0) s_nt = fmaxf(sqrtf(red[0]), 1e-12f);
    __syncthreads();
    g_nvarv[d] = vv / s_nv;
    g_nvart[d] = vt / s_nt;
}

// final fused head -> out[0..31]
__global__ void final_kernel(const float* __restrict__ fw, const float* __restrict__ fb,
                             float* __restrict__ out) {
    int b = blockIdx.x;
    int tid = threadIdx.x;
    float acc = 0.f;
    for (int d = tid; d < Dn; d += 256) {
        float vc = g_vcls[b*Dn + d], tc = g_tcls[b*Dn + d];
        float sv = vc * (1.f + g_nvarv[d]);
        float st = tc * (1.f + g_nvart[d]);
        float f = 0.5f * (sv * st + g_vemb[b*Dn + d] * g_temb[b*Dn + d]);
        acc += f * fw[d];
    }
    __shared__ float red[256];
    red[tid] = acc; __syncthreads();
    for (int o = 128; o > 0; o >>= 1) { if (tid < o) red[tid] += red[tid + o]; __syncthreads(); }
    if (tid == 0) out[b] = red[0] + fb[0] + 0.1f * g_lam[b] - 0.5f;
}

__global__ void finalize_kernel(float* __restrict__ out, int out_size) {
    int t = threadIdx.x;  // 32
    float a = g_rowloss[t], p = g_per[t];
    for (int o = 16; o; o >>= 1) {
        a += __shfl_xor_sync(0xffffffffu, a, o);
        p += __shfl_xor_sync(0xffffffffu, p, o);
    }
    if (t == 0) { out[32] = a / 32.f; out[33] = p / 32.f; }
    for (int i = 34 + t; i < out_size; i += 32) out[i] = 0.f;
}

// ---------------- launch ----------------
extern "C" void kernel_launch(void* const* d_in, const int* in_sizes, int n_in,
                              void* d_out, int out_size) {
    const float* vis   = (const float*)d_in[0];
    const float* txt   = (const float*)d_in[1];
    const float* sent  = (const float*)d_in[2];
    const int*   lens  = (const int*)d_in[3];
    const float* fc1w  = (const float*)d_in[4];
    const float* fc1b  = (const float*)d_in[5];
    const float* fc2w  = (const float*)d_in[6];
    const float* fc2b  = (const float*)d_in[7];
    const float* c1w   = (const float*)d_in[8];
    const float* c1b   = (const float*)d_in[9];
    const float* c2w   = (const float*)d_in[10];
    const float* c2b   = (const float*)d_in[11];
    const float* finw  = (const float*)d_in[12];
    const float* finb  = (const float*)d_in[13];
    float* out = (float*)d_out;

    conv_pre<<<1, 128>>>(c1w, c1b, c2w, c2b);
    zero_rc<<<(Bsz*Tn + 255) / 256, 256>>>();
    cvt_w1 <<<(Dn*Dn/4 + 255) / 256, 256>>>(fc1w);
    cvt_txt<<<(Bsz*Tn*Dn/4 + 255) / 256, 256>>>(txt);
    cvt_vis<<<(Bsz*Vn*Dn/4 + 255) / 256, 256>>>(vis);

    mma_gemm<<<dim3(4, 2, Bsz), 256>>>(0, nullptr, nullptr);   // bmm -> g_S
    conv_kernel<<<dim3(8, 7, Bsz), dim3(64, 4)>>>(c2b);
    act_kernel<<<(Bsz*Tn + 255) / 256, 256>>>();
    cls_kernel<<<dim3(3, Bsz), 256>>>(vis, txt);
    mma_gemm<<<dim3(6, 128, 1), 256>>>(1, fc1b, fc2w);         // fc -> g_pred
    loss1_kernel<<<Bsz, 512>>>(sent, lens, fc2b);
    emb_kernel<<<dim3(Bsz, 2), 256>>>(fc1w, fc1b);
    tail1_kernel<<<1, 1024>>>(fc2w, fc2b);
    contrast_kernel<<<Bsz, 1024>>>();
    varsem_kernel<<<1, Dn>>>();
    final_kernel<<<Bsz, 256>>>(finw, finb, out);
    finalize_kernel<<<1, 32>>>(out, out_size);
}